// round 2
// baseline (speedup 1.0000x reference)
#include <cuda_runtime.h>
#include <math.h>

// Problem constants
#define BSZ    32
#define NSEQ   256
#define HDIM   512
#define NHEADS 8
#define DHEAD  64
#define FDIM   2048
#define LNUM   8
#define MROWS  (BSZ * NSEQ)   // 8192

// ---------------------------------------------------------------------------
// Scratch (static device globals; no runtime allocation allowed)
// ---------------------------------------------------------------------------
__device__ float g_y  [MROWS * HDIM];   // post-LN activations
__device__ float g_q  [MROWS * HDIM];
__device__ float g_k  [MROWS * HDIM];
__device__ float g_v  [MROWS * HDIM];
__device__ float g_ctx[MROWS * HDIM];
__device__ float g_ffn[MROWS * FDIM];

// ---------------------------------------------------------------------------
// LayerNorm: one block (256 threads) per row of 512; exact two-pass
// ---------------------------------------------------------------------------
__global__ void ln_kernel(const float* __restrict__ x,
                          const float* __restrict__ gs,
                          const float* __restrict__ gb,
                          float* __restrict__ y) {
    __shared__ float red[8];
    const int row = blockIdx.x;
    const int tid = threadIdx.x;
    const float* xr = x + (size_t)row * HDIM;

    float v0 = xr[tid];
    float v1 = xr[tid + 256];

    // mean
    float s = v0 + v1;
    #pragma unroll
    for (int o = 16; o; o >>= 1) s += __shfl_xor_sync(0xffffffffu, s, o);
    if ((tid & 31) == 0) red[tid >> 5] = s;
    __syncthreads();
    if (tid < 8) {
        float t = red[tid];
        #pragma unroll
        for (int o = 4; o; o >>= 1) t += __shfl_xor_sync(0xffu, t, o);
        if (tid == 0) red[0] = t;
    }
    __syncthreads();
    const float mu = red[0] * (1.0f / HDIM);
    __syncthreads();

    // variance
    const float d0 = v0 - mu, d1 = v1 - mu;
    float sq = d0 * d0 + d1 * d1;
    #pragma unroll
    for (int o = 16; o; o >>= 1) sq += __shfl_xor_sync(0xffffffffu, sq, o);
    if ((tid & 31) == 0) red[tid >> 5] = sq;
    __syncthreads();
    if (tid < 8) {
        float t = red[tid];
        #pragma unroll
        for (int o = 4; o; o >>= 1) t += __shfl_xor_sync(0xffu, t, o);
        if (tid == 0) red[0] = t;
    }
    __syncthreads();
    const float inv = rsqrtf(red[0] * (1.0f / HDIM) + 1e-5f);

    float* yr = y + (size_t)row * HDIM;
    yr[tid]       = d0 * inv * gs[tid]       + gb[tid];
    yr[tid + 256] = d1 * inv * gs[tid + 256] + gb[tid + 256];
}

// ---------------------------------------------------------------------------
// SGEMM: C[M,N] = epi(A[M,K] @ W[K,N] + bias[N])
//   EPI 0: val = (acc + bias) * scale            (Q/K/V projection)
//   EPI 2: val = gelu_exact(acc + bias)          (FFN up-proj)
//   EPI 3: val = C[m,n] + acc + bias             (residual add, in-place on C)
// Tile 128x128, BK=16, 256 threads, 8x8 per thread.
// ---------------------------------------------------------------------------
template <int EPI>
__global__ __launch_bounds__(256, 2)
void sgemm_kernel(const float* __restrict__ A, const float* __restrict__ W,
                  const float* __restrict__ bias, float* __restrict__ C,
                  int M, int Ncols, int K, float scale) {
    __shared__ __align__(16) float As[16][128];
    __shared__ __align__(16) float Bs[16][128];

    const int tid = threadIdx.x;
    const int m0 = blockIdx.y * 128;
    const int n0 = blockIdx.x * 128;
    const int tm = (tid >> 4) * 8;   // 0..120
    const int tn = (tid & 15) * 8;   // 0..120

    float acc[8][8] = {};

    for (int k0 = 0; k0 < K; k0 += 16) {
        // Load A tile (128 rows x 16 cols), store transposed As[k][m]
        #pragma unroll
        for (int i = 0; i < 2; i++) {
            int idx = tid + i * 256;            // 0..511 float4 slots
            int ar  = idx >> 2;                 // row 0..127
            int ac4 = idx & 3;                  // float4 col 0..3
            float4 av = *(const float4*)(A + (size_t)(m0 + ar) * K + k0 + ac4 * 4);
            As[ac4 * 4 + 0][ar] = av.x;
            As[ac4 * 4 + 1][ar] = av.y;
            As[ac4 * 4 + 2][ar] = av.z;
            As[ac4 * 4 + 3][ar] = av.w;
        }
        // Load B tile (16 rows x 128 cols)
        #pragma unroll
        for (int i = 0; i < 2; i++) {
            int idx = tid + i * 256;
            int br  = idx >> 5;                 // row 0..15
            int bc4 = idx & 31;                 // float4 col 0..31
            *(float4*)(&Bs[br][bc4 * 4]) =
                *(const float4*)(W + (size_t)(k0 + br) * Ncols + n0 + bc4 * 4);
        }
        __syncthreads();

        #pragma unroll
        for (int kk = 0; kk < 16; kk++) {
            float a[8], b[8];
            #pragma unroll
            for (int i = 0; i < 8; i++) a[i] = As[kk][tm + i];
            #pragma unroll
            for (int j = 0; j < 8; j++) b[j] = Bs[kk][tn + j];
            #pragma unroll
            for (int i = 0; i < 8; i++)
                #pragma unroll
                for (int j = 0; j < 8; j++)
                    acc[i][j] = fmaf(a[i], b[j], acc[i][j]);
        }
        __syncthreads();
    }

    // Epilogue
    #pragma unroll
    for (int i = 0; i < 8; i++) {
        const size_t mrow = (size_t)(m0 + tm + i) * Ncols;
        #pragma unroll
        for (int j = 0; j < 8; j++) {
            const int n = n0 + tn + j;
            float val = acc[i][j] + bias[n];
            if (EPI == 0) {
                val *= scale;
            } else if (EPI == 2) {
                val = 0.5f * val * (1.0f + erff(val * 0.70710678118654752f));
            } else if (EPI == 3) {
                val += C[mrow + n];
            }
            C[mrow + n] = val;
        }
    }
}

// ---------------------------------------------------------------------------
// Fused attention: one block per (b, h). K^T and V staged in shared memory,
// one warp per query row (8 warps, 32 rows each), register softmax.
// q is already scaled by D^-0.5 in the projection epilogue.
// ---------------------------------------------------------------------------
#define ATTN_SMEM ((64 * 256 + 256 * 64 + 8 * 256) * 4)   // 139264 bytes

__global__ void attn_kernel(const float* __restrict__ q,
                            const float* __restrict__ k,
                            const float* __restrict__ v,
                            const float* __restrict__ bias,
                            float* __restrict__ ctx) {
    extern __shared__ float sm[];
    float* Ks = sm;                    // [d][j] : Ks[d*256 + j]
    float* Vs = sm + 64 * 256;         // [j][d] : Vs[j*64 + d]
    float* Ps = sm + 2 * 64 * 256;     // [warp][256]

    const int bh   = blockIdx.x;
    const int b    = bh >> 3;
    const int h    = bh & 7;
    const int tid  = threadIdx.x;
    const int warp = tid >> 5;
    const int lane = tid & 31;

    const float* kbase = k + (size_t)b * NSEQ * HDIM + h * DHEAD;
    const float* vbase = v + (size_t)b * NSEQ * HDIM + h * DHEAD;

    // Stage K (transposed) and V
    for (int idx = tid; idx < NSEQ * DHEAD; idx += 256) {
        const int j = idx >> 6;
        const int d = idx & 63;
        Ks[d * 256 + j] = kbase[(size_t)j * HDIM + d];
        Vs[idx]         = vbase[(size_t)j * HDIM + d];
    }
    __syncthreads();

    const float* qbase = q + (size_t)b * NSEQ * HDIM + h * DHEAD;
    const float* bbase = bias + (size_t)bh * NSEQ * NSEQ;
    float* cbase = ctx + (size_t)b * NSEQ * HDIM + h * DHEAD;

    for (int row = warp; row < NSEQ; row += 8) {
        const float q0 = qbase[(size_t)row * HDIM + lane];
        const float q1 = qbase[(size_t)row * HDIM + 32 + lane];

        float s[8];
        #pragma unroll
        for (int t = 0; t < 8; t++)
            s[t] = bbase[(size_t)row * NSEQ + t * 32 + lane];

        #pragma unroll
        for (int d = 0; d < 64; d++) {
            const float qd = __shfl_sync(0xffffffffu, (d < 32) ? q0 : q1, d & 31);
            const float* krow = Ks + d * 256 + lane;
            #pragma unroll
            for (int t = 0; t < 8; t++)
                s[t] = fmaf(qd, krow[t * 32], s[t]);
        }

        // softmax over the row (8 regs x 32 lanes = 256 entries)
        float mx = s[0];
        #pragma unroll
        for (int t = 1; t < 8; t++) mx = fmaxf(mx, s[t]);
        #pragma unroll
        for (int o = 16; o; o >>= 1) mx = fmaxf(mx, __shfl_xor_sync(0xffffffffu, mx, o));
        float sum = 0.0f;
        #pragma unroll
        for (int t = 0; t < 8; t++) { s[t] = expf(s[t] - mx); sum += s[t]; }
        #pragma unroll
        for (int o = 16; o; o >>= 1) sum += __shfl_xor_sync(0xffffffffu, sum, o);
        const float inv = 1.0f / sum;
        #pragma unroll
        for (int t = 0; t < 8; t++)
            Ps[warp * 256 + t * 32 + lane] = s[t] * inv;
        __syncwarp();

        // ctx row: lane handles dims (lane, lane+32)
        float c0 = 0.0f, c1 = 0.0f;
        const float* pw = Ps + warp * 256;
        #pragma unroll 8
        for (int j = 0; j < 256; j++) {
            const float p = pw[j];
            c0 = fmaf(p, Vs[j * 64 + lane],      c0);
            c1 = fmaf(p, Vs[j * 64 + 32 + lane], c1);
        }
        cbase[(size_t)row * HDIM + lane]      = c0;
        cbase[(size_t)row * HDIM + 32 + lane] = c1;
        __syncwarp();
    }
}

// ---------------------------------------------------------------------------
// Host launcher
// ---------------------------------------------------------------------------
extern "C" void kernel_launch(void* const* d_in, const int* in_sizes, int n_in,
                              void* d_out, int out_size) {
    const float* x_in      = (const float*)d_in[0];
    const float* attn_bias = (const float*)d_in[1];
    const float* ln1_s     = (const float*)d_in[2];
    const float* ln1_b     = (const float*)d_in[3];
    const float* wq        = (const float*)d_in[4];
    const float* bq        = (const float*)d_in[5];
    const float* wk        = (const float*)d_in[6];
    const float* bk        = (const float*)d_in[7];
    const float* wv        = (const float*)d_in[8];
    const float* bv        = (const float*)d_in[9];
    const float* wo        = (const float*)d_in[10];
    const float* bo        = (const float*)d_in[11];
    const float* ln2_s     = (const float*)d_in[12];
    const float* ln2_b     = (const float*)d_in[13];
    const float* w1        = (const float*)d_in[14];
    const float* b1        = (const float*)d_in[15];
    const float* w2        = (const float*)d_in[16];
    const float* b2        = (const float*)d_in[17];

    float* X = (float*)d_out;   // residual stream lives in the output buffer

    float *yb, *qb, *kb, *vb, *cb, *fb;
    cudaGetSymbolAddress((void**)&yb, g_y);
    cudaGetSymbolAddress((void**)&qb, g_q);
    cudaGetSymbolAddress((void**)&kb, g_k);
    cudaGetSymbolAddress((void**)&vb, g_v);
    cudaGetSymbolAddress((void**)&cb, g_ctx);
    cudaGetSymbolAddress((void**)&fb, g_ffn);

    cudaFuncSetAttribute(attn_kernel,
                         cudaFuncAttributeMaxDynamicSharedMemorySize, ATTN_SMEM);

    cudaMemcpyAsync(X, x_in, (size_t)MROWS * HDIM * sizeof(float),
                    cudaMemcpyDeviceToDevice);

    const dim3 gB(256);
    const dim3 gProj(HDIM / 128, MROWS / 128);   // (4, 64)
    const dim3 gFfn1(FDIM / 128, MROWS / 128);   // (16, 64)
    const float qscale = 0.125f;                 // 64^-0.5

    for (int l = 0; l < LNUM; l++) {
        const float* wq_l = wq + (size_t)l * HDIM * HDIM;
        const float* wk_l = wk + (size_t)l * HDIM * HDIM;
        const float* wv_l = wv + (size_t)l * HDIM * HDIM;
        const float* wo_l = wo + (size_t)l * HDIM * HDIM;
        const float* w1_l = w1 + (size_t)l * HDIM * FDIM;
        const float* w2_l = w2 + (size_t)l * FDIM * HDIM;

        // --- attention block ---
        ln_kernel<<<MROWS, gB>>>(X, ln1_s + l * HDIM, ln1_b + l * HDIM, yb);
        sgemm_kernel<0><<<gProj, gB>>>(yb, wq_l, bq + l * HDIM, qb,
                                       MROWS, HDIM, HDIM, qscale);
        sgemm_kernel<0><<<gProj, gB>>>(yb, wk_l, bk + l * HDIM, kb,
                                       MROWS, HDIM, HDIM, 1.0f);
        sgemm_kernel<0><<<gProj, gB>>>(yb, wv_l, bv + l * HDIM, vb,
                                       MROWS, HDIM, HDIM, 1.0f);
        attn_kernel<<<BSZ * NHEADS, gB, ATTN_SMEM>>>(qb, kb, vb, attn_bias, cb);
        sgemm_kernel<3><<<gProj, gB>>>(cb, wo_l, bo + l * HDIM, X,
                                       MROWS, HDIM, HDIM, 1.0f);

        // --- FFN block ---
        ln_kernel<<<MROWS, gB>>>(X, ln2_s + l * HDIM, ln2_b + l * HDIM, yb);
        sgemm_kernel<2><<<gFfn1, gB>>>(yb, w1_l, b1 + l * FDIM, fb,
                                       MROWS, FDIM, HDIM, 1.0f);
        sgemm_kernel<3><<<gProj, gB>>>(fb, w2_l, b2 + l * HDIM, X,
                                       MROWS, HDIM, FDIM, 1.0f);
    }
}

// round 5
// speedup vs baseline: 2.2887x; 2.2887x over previous
#include <cuda_runtime.h>
#include <math.h>
#include <stdint.h>

// Problem constants
#define BSZ    32
#define NSEQ   256
#define HDIM   512
#define NHEADS 8
#define DHEAD  64
#define FDIM   2048
#define LNUM   8
#define MROWS  (BSZ * NSEQ)   // 8192

// ---------------------------------------------------------------------------
// Scratch (static device globals; no runtime allocation allowed)
// ---------------------------------------------------------------------------
__device__ float g_y  [MROWS * HDIM];
__device__ float g_q  [MROWS * HDIM];
__device__ float g_k  [MROWS * HDIM];
__device__ float g_v  [MROWS * HDIM];
__device__ float g_ctx[MROWS * HDIM];
__device__ float g_ffn[MROWS * FDIM];
// Transposed weights: Wt[n][k] = W[k][n] (tf32-rounded)
__device__ float g_wqt[LNUM * HDIM * HDIM];
__device__ float g_wkt[LNUM * HDIM * HDIM];
__device__ float g_wvt[LNUM * HDIM * HDIM];
__device__ float g_wot[LNUM * HDIM * HDIM];
__device__ float g_w1t[LNUM * HDIM * FDIM];
__device__ float g_w2t[LNUM * FDIM * HDIM];

// ---------------------------------------------------------------------------
// Helpers
// ---------------------------------------------------------------------------
__device__ __forceinline__ float to_tf32(float x) {
    float r;
    asm("cvt.rna.tf32.f32 %0, %1;" : "=f"(r) : "f"(x));
    return r;
}

__device__ __forceinline__ void cp_async16(void* dst, const void* src) {
    uint32_t d;
    asm("{ .reg .u64 t; cvta.to.shared.u64 t, %1; cvt.u32.u64 %0, t; }"
        : "=r"(d) : "l"(dst));
    asm volatile("cp.async.cg.shared.global [%0], [%1], 16;" :: "r"(d), "l"(src));
}

__device__ __forceinline__ void mma_tf32(float* d, const uint32_t* a, const uint32_t* b) {
    asm volatile(
        "mma.sync.aligned.m16n8k8.row.col.f32.tf32.tf32.f32 "
        "{%0,%1,%2,%3}, {%4,%5,%6,%7}, {%8,%9}, {%0,%1,%2,%3};"
        : "+f"(d[0]), "+f"(d[1]), "+f"(d[2]), "+f"(d[3])
        : "r"(a[0]), "r"(a[1]), "r"(a[2]), "r"(a[3]), "r"(b[0]), "r"(b[1]));
}

// ---------------------------------------------------------------------------
// Weight transpose: dst[n][k] = tf32(src[k][n]), per layer (blockIdx.z)
// ---------------------------------------------------------------------------
__global__ void transpose_kernel(const float* __restrict__ src,
                                 float* __restrict__ dst, int R, int C) {
    __shared__ float t[32][33];
    const size_t lo = (size_t)blockIdx.z * R * C;
    const int c0 = blockIdx.x * 32, r0 = blockIdx.y * 32;
    #pragma unroll
    for (int i = 0; i < 32; i += 8)
        t[threadIdx.y + i][threadIdx.x] =
            src[lo + (size_t)(r0 + threadIdx.y + i) * C + c0 + threadIdx.x];
    __syncthreads();
    #pragma unroll
    for (int i = 0; i < 32; i += 8)
        dst[lo + (size_t)(c0 + threadIdx.y + i) * R + r0 + threadIdx.x] =
            to_tf32(t[threadIdx.x][threadIdx.y + i]);
}

// ---------------------------------------------------------------------------
// tf32 mma.sync GEMM: C[M,N] = epi(A[M,K] @ Bt[N,K]^T + bias[N])
//   EPI 0: (acc+bias)*scale   EPI 2: tf32(gelu(acc+bias))   EPI 3: C += acc+bias
// Tile 128x128x32, 128 threads (4 warps, 2x2), warp tile 64x64.
// Smem XOR swizzle: float (m, k) stored at m*32 + (k ^ (4*(m&7))).
// ---------------------------------------------------------------------------
#define TILE_B   16384                 // 128 x 32 floats
#define STAGE_B  (2 * TILE_B)          // A tile + B tile
#define GEMM_SMEM (2 * STAGE_B)        // 2 stages = 65536

__device__ __forceinline__ void load_chunk(const float* __restrict__ A,
                                           const float* __restrict__ Bt,
                                           int m0, int n0, int K, int c,
                                           char* stage, int tid) {
    const float* Ap = A  + (size_t)m0 * K + c * 32;
    const float* Bp = Bt + (size_t)n0 * K + c * 32;
    float* As = (float*)stage;
    float* Bs = (float*)(stage + TILE_B);
    #pragma unroll
    for (int i = 0; i < 8; i++) {
        const int id  = tid + i * 128;       // 0..1023
        const int row = id >> 3;
        const int c4  = id & 7;
        const int off = row * 32 + ((c4 * 4) ^ ((row & 7) * 4));
        cp_async16(As + off, Ap + (size_t)row * K + c4 * 4);
        cp_async16(Bs + off, Bp + (size_t)row * K + c4 * 4);
    }
    asm volatile("cp.async.commit_group;" ::: "memory");
}

template <int EPI>
__global__ __launch_bounds__(128, 2)
void tgemm_kernel(const float* __restrict__ A, const float* __restrict__ Bt,
                  const float* __restrict__ bias, float* __restrict__ C,
                  int Ncols, int K, float scale) {
    extern __shared__ __align__(16) char smem[];

    const int tid    = threadIdx.x;
    const int warp   = tid >> 5;
    const int lane   = tid & 31;
    const int warp_m = (warp >> 1) * 64;
    const int warp_n = (warp & 1) * 64;
    const int row    = lane >> 2;       // 0..7
    const int col    = lane & 3;        // 0..3
    const int cswz   = row * 4;

    const int m0 = blockIdx.y * 128;
    const int n0 = blockIdx.x * 128;

    float d[4][8][4];
    #pragma unroll
    for (int mt = 0; mt < 4; mt++)
        #pragma unroll
        for (int nt = 0; nt < 8; nt++)
            #pragma unroll
            for (int j = 0; j < 4; j++) d[mt][nt][j] = 0.0f;

    const int nch = K / 32;
    load_chunk(A, Bt, m0, n0, K, 0, smem, tid);

    for (int c = 0; c < nch; c++) {
        if (c + 1 < nch) {
            load_chunk(A, Bt, m0, n0, K, c + 1, smem + ((c + 1) & 1) * STAGE_B, tid);
            asm volatile("cp.async.wait_group 1;" ::: "memory");
        } else {
            asm volatile("cp.async.wait_group 0;" ::: "memory");
        }
        __syncthreads();

        const uint32_t* As = (const uint32_t*)(smem + (c & 1) * STAGE_B);
        const uint32_t* Bs = (const uint32_t*)(smem + (c & 1) * STAGE_B + TILE_B);

        #pragma unroll
        for (int ks = 0; ks < 4; ks++) {
            const int koff  = ((ks * 8) | col) ^ cswz;
            const int koff2 = koff ^ 4;

            uint32_t a[4][4];
            #pragma unroll
            for (int mt = 0; mt < 4; mt++) {
                const uint32_t* ap = As + (warp_m + mt * 16 + row) * 32;
                a[mt][0] = ap[koff];
                a[mt][1] = ap[8 * 32 + koff];
                a[mt][2] = ap[koff2];
                a[mt][3] = ap[8 * 32 + koff2];
            }
            uint32_t b[8][2];
            #pragma unroll
            for (int nt = 0; nt < 8; nt++) {
                const uint32_t* bp = Bs + (warp_n + nt * 8 + row) * 32;
                b[nt][0] = bp[koff];
                b[nt][1] = bp[koff2];
            }
            #pragma unroll
            for (int mt = 0; mt < 4; mt++)
                #pragma unroll
                for (int nt = 0; nt < 8; nt++)
                    mma_tf32(d[mt][nt], a[mt], b[nt]);
        }
        __syncthreads();
    }

    // Epilogue
    #pragma unroll
    for (int nt = 0; nt < 8; nt++) {
        const int nb = n0 + warp_n + nt * 8 + col * 2;
        const float2 bv = *(const float2*)(bias + nb);
        #pragma unroll
        for (int mt = 0; mt < 4; mt++) {
            const int m1 = m0 + warp_m + mt * 16 + row;
            #pragma unroll
            for (int half = 0; half < 2; half++) {
                float* crow = C + (size_t)(m1 + half * 8) * Ncols + nb;
                float v0 = d[mt][nt][half * 2 + 0] + bv.x;
                float v1 = d[mt][nt][half * 2 + 1] + bv.y;
                if (EPI == 0) {
                    v0 *= scale; v1 *= scale;
                } else if (EPI == 2) {
                    v0 = to_tf32(0.5f * v0 * (1.0f + erff(v0 * 0.70710678118654752f)));
                    v1 = to_tf32(0.5f * v1 * (1.0f + erff(v1 * 0.70710678118654752f)));
                } else if (EPI == 3) {
                    const float2 old = *(const float2*)crow;
                    v0 += old.x; v1 += old.y;
                }
                *(float2*)crow = make_float2(v0, v1);
            }
        }
    }
}

// ---------------------------------------------------------------------------
// LayerNorm: one block (256 threads) per row of 512; exact two-pass.
// Output rounded to tf32 (it only feeds tensor-core GEMMs).
// ---------------------------------------------------------------------------
__global__ void ln_kernel(const float* __restrict__ x,
                          const float* __restrict__ gs,
                          const float* __restrict__ gb,
                          float* __restrict__ y) {
    __shared__ float red[8];
    const int row = blockIdx.x;
    const int tid = threadIdx.x;
    const float* xr = x + (size_t)row * HDIM;

    float v0 = xr[tid];
    float v1 = xr[tid + 256];

    float s = v0 + v1;
    #pragma unroll
    for (int o = 16; o; o >>= 1) s += __shfl_xor_sync(0xffffffffu, s, o);
    if ((tid & 31) == 0) red[tid >> 5] = s;
    __syncthreads();
    if (tid < 8) {
        float t = red[tid];
        #pragma unroll
        for (int o = 4; o; o >>= 1) t += __shfl_xor_sync(0xffu, t, o);
        if (tid == 0) red[0] = t;
    }
    __syncthreads();
    const float mu = red[0] * (1.0f / HDIM);
    __syncthreads();

    const float d0 = v0 - mu, d1 = v1 - mu;
    float sq = d0 * d0 + d1 * d1;
    #pragma unroll
    for (int o = 16; o; o >>= 1) sq += __shfl_xor_sync(0xffffffffu, sq, o);
    if ((tid & 31) == 0) red[tid >> 5] = sq;
    __syncthreads();
    if (tid < 8) {
        float t = red[tid];
        #pragma unroll
        for (int o = 4; o; o >>= 1) t += __shfl_xor_sync(0xffu, t, o);
        if (tid == 0) red[0] = t;
    }
    __syncthreads();
    const float inv = rsqrtf(red[0] * (1.0f / HDIM) + 1e-5f);

    float* yr = y + (size_t)row * HDIM;
    yr[tid]       = to_tf32(d0 * inv * gs[tid]       + gb[tid]);
    yr[tid + 256] = to_tf32(d1 * inv * gs[tid + 256] + gb[tid + 256]);
}

// ---------------------------------------------------------------------------
// Fused attention: one block per (b,h). ctx output rounded to tf32
// (it only feeds the wo GEMM).
// ---------------------------------------------------------------------------
#define ATTN_SMEM ((64 * 256 + 256 * 64 + 8 * 256) * 4)

__global__ void attn_kernel(const float* __restrict__ q,
                            const float* __restrict__ k,
                            const float* __restrict__ v,
                            const float* __restrict__ bias,
                            float* __restrict__ ctx) {
    extern __shared__ float sm[];
    float* Ks = sm;
    float* Vs = sm + 64 * 256;
    float* Ps = sm + 2 * 64 * 256;

    const int bh   = blockIdx.x;
    const int b    = bh >> 3;
    const int h    = bh & 7;
    const int tid  = threadIdx.x;
    const int warp = tid >> 5;
    const int lane = tid & 31;

    const float* kbase = k + (size_t)b * NSEQ * HDIM + h * DHEAD;
    const float* vbase = v + (size_t)b * NSEQ * HDIM + h * DHEAD;

    for (int idx = tid; idx < NSEQ * DHEAD; idx += 256) {
        const int j = idx >> 6;
        const int d = idx & 63;
        Ks[d * 256 + j] = kbase[(size_t)j * HDIM + d];
        Vs[idx]         = vbase[(size_t)j * HDIM + d];
    }
    __syncthreads();

    const float* qbase = q + (size_t)b * NSEQ * HDIM + h * DHEAD;
    const float* bbase = bias + (size_t)bh * NSEQ * NSEQ;
    float* cbase = ctx + (size_t)b * NSEQ * HDIM + h * DHEAD;

    for (int rowq = warp; rowq < NSEQ; rowq += 8) {
        const float q0 = qbase[(size_t)rowq * HDIM + lane];
        const float q1 = qbase[(size_t)rowq * HDIM + 32 + lane];

        float s[8];
        #pragma unroll
        for (int t = 0; t < 8; t++)
            s[t] = bbase[(size_t)rowq * NSEQ + t * 32 + lane];

        #pragma unroll
        for (int d = 0; d < 64; d++) {
            const float qd = __shfl_sync(0xffffffffu, (d < 32) ? q0 : q1, d & 31);
            const float* krow = Ks + d * 256 + lane;
            #pragma unroll
            for (int t = 0; t < 8; t++)
                s[t] = fmaf(qd, krow[t * 32], s[t]);
        }

        float mx = s[0];
        #pragma unroll
        for (int t = 1; t < 8; t++) mx = fmaxf(mx, s[t]);
        #pragma unroll
        for (int o = 16; o; o >>= 1) mx = fmaxf(mx, __shfl_xor_sync(0xffffffffu, mx, o));
        float sum = 0.0f;
        #pragma unroll
        for (int t = 0; t < 8; t++) { s[t] = expf(s[t] - mx); sum += s[t]; }
        #pragma unroll
        for (int o = 16; o; o >>= 1) sum += __shfl_xor_sync(0xffffffffu, sum, o);
        const float inv = 1.0f / sum;
        #pragma unroll
        for (int t = 0; t < 8; t++)
            Ps[warp * 256 + t * 32 + lane] = s[t] * inv;
        __syncwarp();

        float c0 = 0.0f, c1 = 0.0f;
        const float* pw = Ps + warp * 256;
        #pragma unroll 8
        for (int j = 0; j < 256; j++) {
            const float p = pw[j];
            c0 = fmaf(p, Vs[j * 64 + lane],      c0);
            c1 = fmaf(p, Vs[j * 64 + 32 + lane], c1);
        }
        cbase[(size_t)rowq * HDIM + lane]      = to_tf32(c0);
        cbase[(size_t)rowq * HDIM + 32 + lane] = to_tf32(c1);
        __syncwarp();
    }
}

// ---------------------------------------------------------------------------
// Host launcher
// ---------------------------------------------------------------------------
extern "C" void kernel_launch(void* const* d_in, const int* in_sizes, int n_in,
                              void* d_out, int out_size) {
    const float* x_in      = (const float*)d_in[0];
    const float* attn_bias = (const float*)d_in[1];
    const float* ln1_s     = (const float*)d_in[2];
    const float* ln1_b     = (const float*)d_in[3];
    const float* wq        = (const float*)d_in[4];
    const float* bq        = (const float*)d_in[5];
    const float* wk        = (const float*)d_in[6];
    const float* bk        = (const float*)d_in[7];
    const float* wv        = (const float*)d_in[8];
    const float* bv        = (const float*)d_in[9];
    const float* wo        = (const float*)d_in[10];
    const float* bo        = (const float*)d_in[11];
    const float* ln2_s     = (const float*)d_in[12];
    const float* ln2_b     = (const float*)d_in[13];
    const float* w1        = (const float*)d_in[14];
    const float* b1        = (const float*)d_in[15];
    const float* w2        = (const float*)d_in[16];
    const float* b2        = (const float*)d_in[17];

    float* X = (float*)d_out;

    float *yb, *qb, *kb, *vb, *cb, *fb;
    float *wqt, *wkt, *wvt, *wot, *w1t, *w2t;
    cudaGetSymbolAddress((void**)&yb, g_y);
    cudaGetSymbolAddress((void**)&qb, g_q);
    cudaGetSymbolAddress((void**)&kb, g_k);
    cudaGetSymbolAddress((void**)&vb, g_v);
    cudaGetSymbolAddress((void**)&cb, g_ctx);
    cudaGetSymbolAddress((void**)&fb, g_ffn);
    cudaGetSymbolAddress((void**)&wqt, g_wqt);
    cudaGetSymbolAddress((void**)&wkt, g_wkt);
    cudaGetSymbolAddress((void**)&wvt, g_wvt);
    cudaGetSymbolAddress((void**)&wot, g_wot);
    cudaGetSymbolAddress((void**)&w1t, g_w1t);
    cudaGetSymbolAddress((void**)&w2t, g_w2t);

    cudaFuncSetAttribute(attn_kernel,
                         cudaFuncAttributeMaxDynamicSharedMemorySize, ATTN_SMEM);
    cudaFuncSetAttribute(tgemm_kernel<0>,
                         cudaFuncAttributeMaxDynamicSharedMemorySize, GEMM_SMEM);
    cudaFuncSetAttribute(tgemm_kernel<2>,
                         cudaFuncAttributeMaxDynamicSharedMemorySize, GEMM_SMEM);
    cudaFuncSetAttribute(tgemm_kernel<3>,
                         cudaFuncAttributeMaxDynamicSharedMemorySize, GEMM_SMEM);

    cudaMemcpyAsync(X, x_in, (size_t)MROWS * HDIM * sizeof(float),
                    cudaMemcpyDeviceToDevice);

    // One-time weight transposes (+ tf32 rounding)
    {
        const dim3 tb(32, 8);
        const dim3 gHH(HDIM / 32, HDIM / 32, LNUM);
        const dim3 gHF(FDIM / 32, HDIM / 32, LNUM);
        const dim3 gFH(HDIM / 32, FDIM / 32, LNUM);
        transpose_kernel<<<gHH, tb>>>(wq, wqt, HDIM, HDIM);
        transpose_kernel<<<gHH, tb>>>(wk, wkt, HDIM, HDIM);
        transpose_kernel<<<gHH, tb>>>(wv, wvt, HDIM, HDIM);
        transpose_kernel<<<gHH, tb>>>(wo, wot, HDIM, HDIM);
        transpose_kernel<<<gHF, tb>>>(w1, w1t, HDIM, FDIM);
        transpose_kernel<<<gFH, tb>>>(w2, w2t, FDIM, HDIM);
    }

    const dim3 gB(256);
    const dim3 tG(128);
    const dim3 gProj(HDIM / 128, MROWS / 128);   // (4, 64)
    const dim3 gFfn1(FDIM / 128, MROWS / 128);   // (16, 64)
    const float qscale = 0.125f;                 // 64^-0.5

    for (int l = 0; l < LNUM; l++) {
        const float* wqt_l = wqt + (size_t)l * HDIM * HDIM;
        const float* wkt_l = wkt + (size_t)l * HDIM * HDIM;
        const float* wvt_l = wvt + (size_t)l * HDIM * HDIM;
        const float* wot_l = wot + (size_t)l * HDIM * HDIM;
        const float* w1t_l = w1t + (size_t)l * HDIM * FDIM;
        const float* w2t_l = w2t + (size_t)l * FDIM * HDIM;

        // --- attention block ---
        ln_kernel<<<MROWS, gB>>>(X, ln1_s + l * HDIM, ln1_b + l * HDIM, yb);
        tgemm_kernel<0><<<gProj, tG, GEMM_SMEM>>>(yb, wqt_l, bq + l * HDIM, qb,
                                                  HDIM, HDIM, qscale);
        tgemm_kernel<0><<<gProj, tG, GEMM_SMEM>>>(yb, wkt_l, bk + l * HDIM, kb,
                                                  HDIM, HDIM, 1.0f);
        tgemm_kernel<0><<<gProj, tG, GEMM_SMEM>>>(yb, wvt_l, bv + l * HDIM, vb,
                                                  HDIM, HDIM, 1.0f);
        attn_kernel<<<BSZ * NHEADS, gB, ATTN_SMEM>>>(qb, kb, vb, attn_bias, cb);
        tgemm_kernel<3><<<gProj, tG, GEMM_SMEM>>>(cb, wot_l, bo + l * HDIM, X,
                                                  HDIM, HDIM, 1.0f);

        // --- FFN block ---
        ln_kernel<<<MROWS, gB>>>(X, ln2_s + l * HDIM, ln2_b + l * HDIM, yb);
        tgemm_kernel<2><<<gFfn1, tG, GEMM_SMEM>>>(yb, w1t_l, b1 + l * FDIM, fb,
                                                  FDIM, HDIM, 1.0f);
        tgemm_kernel<3><<<gProj, tG, GEMM_SMEM>>>(fb, w2t_l, b2 + l * HDIM, X,
                                                  HDIM, FDIM, 1.0f);
    }
}

// round 6
// speedup vs baseline: 3.8008x; 1.6607x over previous
#include <cuda_runtime.h>
#include <math.h>
#include <stdint.h>

// Problem constants
#define BSZ    32
#define NSEQ   256
#define HDIM   512
#define NHEADS 8
#define DHEAD  64
#define FDIM   2048
#define LNUM   8
#define MROWS  (BSZ * NSEQ)   // 8192
#define NBH    (BSZ * NHEADS) // 256

// ---------------------------------------------------------------------------
// Scratch (static device globals; no runtime allocation allowed)
// ---------------------------------------------------------------------------
__device__ float g_y  [MROWS * HDIM];
__device__ float g_q  [MROWS * HDIM];
__device__ float g_k  [MROWS * HDIM];
__device__ float g_v  [MROWS * HDIM];
__device__ float g_ctx[MROWS * HDIM];
__device__ float g_ffn[MROWS * FDIM];
__device__ float g_sc [NBH * NSEQ * NSEQ];     // attention scores / probs
__device__ float g_vt [NBH * DHEAD * NSEQ];    // per-head transposed V
// Transposed weights: Wt[n][k] = W[k][n] (tf32-rounded)
__device__ float g_wqt[LNUM * HDIM * HDIM];
__device__ float g_wkt[LNUM * HDIM * HDIM];
__device__ float g_wvt[LNUM * HDIM * HDIM];
__device__ float g_wot[LNUM * HDIM * HDIM];
__device__ float g_w1t[LNUM * HDIM * FDIM];
__device__ float g_w2t[LNUM * FDIM * HDIM];

// ---------------------------------------------------------------------------
// Helpers
// ---------------------------------------------------------------------------
__device__ __forceinline__ float to_tf32(float x) {
    float r;
    asm("cvt.rna.tf32.f32 %0, %1;" : "=f"(r) : "f"(x));
    return r;
}

__device__ __forceinline__ void cp_async16(void* dst, const void* src) {
    uint32_t d;
    asm("{ .reg .u64 t; cvta.to.shared.u64 t, %1; cvt.u32.u64 %0, t; }"
        : "=r"(d) : "l"(dst));
    asm volatile("cp.async.cg.shared.global [%0], [%1], 16;" :: "r"(d), "l"(src));
}

#define CP_COMMIT() asm volatile("cp.async.commit_group;" ::: "memory")
#define CP_WAIT(n)  asm volatile("cp.async.wait_group %0;" :: "n"(n) : "memory")

__device__ __forceinline__ void mma_tf32(float* d, const uint32_t* a, const uint32_t* b) {
    asm volatile(
        "mma.sync.aligned.m16n8k8.row.col.f32.tf32.tf32.f32 "
        "{%0,%1,%2,%3}, {%4,%5,%6,%7}, {%8,%9}, {%0,%1,%2,%3};"
        : "+f"(d[0]), "+f"(d[1]), "+f"(d[2]), "+f"(d[3])
        : "r"(a[0]), "r"(a[1]), "r"(a[2]), "r"(a[3]), "r"(b[0]), "r"(b[1]));
}

// ---------------------------------------------------------------------------
// Tile loaders: 128 (or 64) rows x 32 k-floats, XOR-swizzled smem
// float (r, k) at r*32 + (k ^ (4*(r&7)))
// ---------------------------------------------------------------------------
__device__ __forceinline__ void load_tile128(const float* __restrict__ base, int lda,
                                             int c, float* sdst, int tid) {
    const float* p = base + c * 32;
    #pragma unroll
    for (int i = 0; i < 8; i++) {
        const int id  = tid + i * 128;
        const int row = id >> 3;
        const int c4  = id & 7;
        const int off = row * 32 + ((c4 * 4) ^ ((row & 7) * 4));
        cp_async16(sdst + off, p + (size_t)row * lda + c4 * 4);
    }
}

__device__ __forceinline__ void load_tile64(const float* __restrict__ base, int lda,
                                            int c, float* sdst, int tid) {
    const float* p = base + c * 32;
    #pragma unroll
    for (int i = 0; i < 4; i++) {
        const int id  = tid + i * 128;
        const int row = id >> 3;
        const int c4  = id & 7;
        const int off = row * 32 + ((c4 * 4) ^ ((row & 7) * 4));
        cp_async16(sdst + off, p + (size_t)row * lda + c4 * 4);
    }
}

// ---------------------------------------------------------------------------
// GEMM core: 128x128 tile, 128 threads (4 warps 2x2, 64x64 each),
// 3-stage cp.async pipeline, single __syncthreads per chunk.
// A rows: m, lda;  B rows: n, ldb;  K % 32 == 0, K >= 64.
// ---------------------------------------------------------------------------
#define TILE_B    16384
#define STAGE_B   32768
#define GSMEM3    (3 * STAGE_B)    // 98304

__device__ __forceinline__ void gemm_main(const float* __restrict__ A, int lda,
                                          const float* __restrict__ B, int ldb,
                                          int K, char* smem, int tid,
                                          float (&d)[4][8][4]) {
    const int warp   = tid >> 5;
    const int lane   = tid & 31;
    const int warp_m = (warp >> 1) * 64;
    const int warp_n = (warp & 1) * 64;
    const int row    = lane >> 2;
    const int col    = lane & 3;
    const int cswz   = row * 4;

    #pragma unroll
    for (int mt = 0; mt < 4; mt++)
        #pragma unroll
        for (int nt = 0; nt < 8; nt++)
            #pragma unroll
            for (int j = 0; j < 4; j++) d[mt][nt][j] = 0.0f;

    const int nch = K / 32;
    load_tile128(A, lda, 0, (float*)smem, tid);
    load_tile128(B, ldb, 0, (float*)(smem + TILE_B), tid);
    CP_COMMIT();
    load_tile128(A, lda, 1, (float*)(smem + STAGE_B), tid);
    load_tile128(B, ldb, 1, (float*)(smem + STAGE_B + TILE_B), tid);
    CP_COMMIT();

    for (int c = 0; c < nch; c++) {
        if (c + 1 < nch) CP_WAIT(1);
        else             CP_WAIT(0);
        __syncthreads();

        if (c + 2 < nch) {
            char* st = smem + ((c + 2) % 3) * STAGE_B;
            load_tile128(A, lda, c + 2, (float*)st, tid);
            load_tile128(B, ldb, c + 2, (float*)(st + TILE_B), tid);
            CP_COMMIT();
        }

        const uint32_t* As = (const uint32_t*)(smem + (c % 3) * STAGE_B);
        const uint32_t* Bs = (const uint32_t*)(smem + (c % 3) * STAGE_B + TILE_B);

        #pragma unroll
        for (int ks = 0; ks < 4; ks++) {
            const int koff  = ((ks * 8) | col) ^ cswz;
            const int koff2 = koff ^ 4;

            uint32_t a[4][4];
            #pragma unroll
            for (int mt = 0; mt < 4; mt++) {
                const uint32_t* ap = As + (warp_m + mt * 16 + row) * 32;
                a[mt][0] = ap[koff];
                a[mt][1] = ap[8 * 32 + koff];
                a[mt][2] = ap[koff2];
                a[mt][3] = ap[8 * 32 + koff2];
            }
            uint32_t b[8][2];
            #pragma unroll
            for (int nt = 0; nt < 8; nt++) {
                const uint32_t* bp = Bs + (warp_n + nt * 8 + row) * 32;
                b[nt][0] = bp[koff];
                b[nt][1] = bp[koff2];
            }
            #pragma unroll
            for (int mt = 0; mt < 4; mt++)
                #pragma unroll
                for (int nt = 0; nt < 8; nt++)
                    mma_tf32(d[mt][nt], a[mt], b[nt]);
        }
    }
}

// ---------------------------------------------------------------------------
// Generic GEMM kernels (weights pre-transposed; lda = ldb = K, ldc = Ncols)
//   EPI 2: tf32(gelu(acc + bias))        EPI 3: C += acc + bias
// ---------------------------------------------------------------------------
template <int EPI>
__global__ __launch_bounds__(128, 2)
void tgemm_kernel(const float* __restrict__ A, const float* __restrict__ Bt,
                  const float* __restrict__ bias, float* __restrict__ C,
                  int Ncols, int K) {
    extern __shared__ __align__(16) char smem[];
    const int tid  = threadIdx.x;
    const int warp = tid >> 5;
    const int lane = tid & 31;
    const int m0 = blockIdx.y * 128;
    const int n0 = blockIdx.x * 128;

    float d[4][8][4];
    gemm_main(A + (size_t)m0 * K, K, Bt + (size_t)n0 * K, K, K, smem, tid, d);

    const int warp_m = (warp >> 1) * 64;
    const int warp_n = (warp & 1) * 64;
    const int row = lane >> 2, col = lane & 3;

    #pragma unroll
    for (int nt = 0; nt < 8; nt++) {
        const int nb = n0 + warp_n + nt * 8 + col * 2;
        const float2 bv = *(const float2*)(bias + nb);
        #pragma unroll
        for (int mt = 0; mt < 4; mt++) {
            const int m1 = m0 + warp_m + mt * 16 + row;
            #pragma unroll
            for (int half = 0; half < 2; half++) {
                float* crow = C + (size_t)(m1 + half * 8) * Ncols + nb;
                float v0 = d[mt][nt][half * 2 + 0] + bv.x;
                float v1 = d[mt][nt][half * 2 + 1] + bv.y;
                if (EPI == 2) {
                    v0 = to_tf32(0.5f * v0 * (1.0f + erff(v0 * 0.70710678118654752f)));
                    v1 = to_tf32(0.5f * v1 * (1.0f + erff(v1 * 0.70710678118654752f)));
                } else if (EPI == 3) {
                    const float2 old = *(const float2*)crow;
                    v0 += old.x; v1 += old.y;
                }
                *(float2*)crow = make_float2(v0, v1);
            }
        }
    }
}

// ---------------------------------------------------------------------------
// Fused QKV projection: grid.x = 12 -> (sel = x>>2) in {q,k,v}, n0 = (x&3)*128
// val = tf32((acc + bias) * scale)
// ---------------------------------------------------------------------------
__global__ __launch_bounds__(128, 2)
void qkv_kernel(const float* __restrict__ A,
                const float* __restrict__ wqt, const float* __restrict__ wkt,
                const float* __restrict__ wvt,
                const float* __restrict__ bq, const float* __restrict__ bk,
                const float* __restrict__ bv,
                float* __restrict__ q, float* __restrict__ k, float* __restrict__ v) {
    extern __shared__ __align__(16) char smem[];
    const int tid  = threadIdx.x;
    const int warp = tid >> 5;
    const int lane = tid & 31;
    const int sel = blockIdx.x >> 2;
    const int n0  = (blockIdx.x & 3) * 128;
    const int m0  = blockIdx.y * 128;

    const float* Bt   = (sel == 0) ? wqt : (sel == 1) ? wkt : wvt;
    const float* bias = (sel == 0) ? bq  : (sel == 1) ? bk  : bv;
    float*       C    = (sel == 0) ? q   : (sel == 1) ? k   : v;
    const float scale = (sel == 0) ? 0.125f : 1.0f;

    float d[4][8][4];
    gemm_main(A + (size_t)m0 * HDIM, HDIM, Bt + (size_t)n0 * HDIM, HDIM, HDIM,
              smem, tid, d);

    const int warp_m = (warp >> 1) * 64;
    const int warp_n = (warp & 1) * 64;
    const int row = lane >> 2, col = lane & 3;

    #pragma unroll
    for (int nt = 0; nt < 8; nt++) {
        const int nb = n0 + warp_n + nt * 8 + col * 2;
        const float2 bvv = *(const float2*)(bias + nb);
        #pragma unroll
        for (int mt = 0; mt < 4; mt++) {
            const int m1 = m0 + warp_m + mt * 16 + row;
            #pragma unroll
            for (int half = 0; half < 2; half++) {
                float* crow = C + (size_t)(m1 + half * 8) * HDIM + nb;
                float v0 = to_tf32((d[mt][nt][half * 2 + 0] + bvv.x) * scale);
                float v1 = to_tf32((d[mt][nt][half * 2 + 1] + bvv.y) * scale);
                *(float2*)crow = make_float2(v0, v1);
            }
        }
    }
}

// ---------------------------------------------------------------------------
// Attention scores: S[bh][q][key] = Q·K^T + attn_bias  (batched, K-dim 64)
// ---------------------------------------------------------------------------
__global__ __launch_bounds__(128, 2)
void s_gemm_kernel(const float* __restrict__ q, const float* __restrict__ k,
                   const float* __restrict__ attn_bias, float* __restrict__ scores) {
    extern __shared__ __align__(16) char smem[];
    const int tid  = threadIdx.x;
    const int warp = tid >> 5;
    const int lane = tid & 31;
    const int bh = blockIdx.z;
    const int b  = bh >> 3, h = bh & 7;
    const int m0 = blockIdx.y * 128;
    const int n0 = blockIdx.x * 128;

    const float* A = q + (size_t)b * NSEQ * HDIM + (size_t)m0 * HDIM + h * DHEAD;
    const float* B = k + (size_t)b * NSEQ * HDIM + (size_t)n0 * HDIM + h * DHEAD;

    float d[4][8][4];
    gemm_main(A, HDIM, B, HDIM, DHEAD, smem, tid, d);

    const float* bm = attn_bias + (size_t)bh * NSEQ * NSEQ;
    float* C = scores + (size_t)bh * NSEQ * NSEQ;

    const int warp_m = (warp >> 1) * 64;
    const int warp_n = (warp & 1) * 64;
    const int row = lane >> 2, col = lane & 3;

    #pragma unroll
    for (int nt = 0; nt < 8; nt++) {
        const int nb = n0 + warp_n + nt * 8 + col * 2;
        #pragma unroll
        for (int mt = 0; mt < 4; mt++) {
            const int m1 = m0 + warp_m + mt * 16 + row;
            #pragma unroll
            for (int half = 0; half < 2; half++) {
                const size_t off = (size_t)(m1 + half * 8) * NSEQ + nb;
                const float2 bb = *(const float2*)(bm + off);
                float v0 = d[mt][nt][half * 2 + 0] + bb.x;
                float v1 = d[mt][nt][half * 2 + 1] + bb.y;
                *(float2*)(C + off) = make_float2(v0, v1);
            }
        }
    }
}

// ---------------------------------------------------------------------------
// Softmax: one warp per row of 256; output tf32-rounded probabilities
// ---------------------------------------------------------------------------
__global__ __launch_bounds__(256)
void softmax_kernel(float* __restrict__ scores) {
    const int r    = blockIdx.x * 8 + (threadIdx.x >> 5);
    const int lane = threadIdx.x & 31;
    float4* p = (float4*)(scores + (size_t)r * NSEQ);

    float4 v0 = p[lane];
    float4 v1 = p[lane + 32];

    float mx = fmaxf(fmaxf(fmaxf(v0.x, v0.y), fmaxf(v0.z, v0.w)),
                     fmaxf(fmaxf(v1.x, v1.y), fmaxf(v1.z, v1.w)));
    #pragma unroll
    for (int o = 16; o; o >>= 1) mx = fmaxf(mx, __shfl_xor_sync(0xffffffffu, mx, o));

    v0.x = expf(v0.x - mx); v0.y = expf(v0.y - mx);
    v0.z = expf(v0.z - mx); v0.w = expf(v0.w - mx);
    v1.x = expf(v1.x - mx); v1.y = expf(v1.y - mx);
    v1.z = expf(v1.z - mx); v1.w = expf(v1.w - mx);

    float sum = v0.x + v0.y + v0.z + v0.w + v1.x + v1.y + v1.z + v1.w;
    #pragma unroll
    for (int o = 16; o; o >>= 1) sum += __shfl_xor_sync(0xffffffffu, sum, o);
    const float inv = 1.0f / sum;

    v0.x = to_tf32(v0.x * inv); v0.y = to_tf32(v0.y * inv);
    v0.z = to_tf32(v0.z * inv); v0.w = to_tf32(v0.w * inv);
    v1.x = to_tf32(v1.x * inv); v1.y = to_tf32(v1.y * inv);
    v1.z = to_tf32(v1.z * inv); v1.w = to_tf32(v1.w * inv);

    p[lane]      = v0;
    p[lane + 32] = v1;
}

// ---------------------------------------------------------------------------
// Per-head V transpose: vt[bh][d][j] = v[b][j][h*64+d]
// ---------------------------------------------------------------------------
__global__ void vt_kernel(const float* __restrict__ v, float* __restrict__ vt) {
    __shared__ float t[32][33];
    const int bh = blockIdx.z;
    const int b  = bh >> 3, h = bh & 7;
    const int j0 = blockIdx.x * 32;
    const int d0 = blockIdx.y * 32;
    const float* src = v + (size_t)b * NSEQ * HDIM + h * DHEAD;
    float* dst = vt + (size_t)bh * DHEAD * NSEQ;
    #pragma unroll
    for (int i = 0; i < 32; i += 8)
        t[threadIdx.y + i][threadIdx.x] =
            src[(size_t)(j0 + threadIdx.y + i) * HDIM + d0 + threadIdx.x];
    __syncthreads();
    #pragma unroll
    for (int i = 0; i < 32; i += 8)
        dst[(size_t)(d0 + threadIdx.y + i) * NSEQ + j0 + threadIdx.x] =
            t[threadIdx.x][threadIdx.y + i];
}

// ---------------------------------------------------------------------------
// PV GEMM: ctx[bh][q][d] = P[q][key] · Vt[d][key]^T  (tile 128x64, K=256)
// 4 warps stacked in m (32 rows each), accumulators 2x8x4.
// ---------------------------------------------------------------------------
#define PV_TILE_A  16384
#define PV_TILE_B  8192
#define PV_STAGE   (PV_TILE_A + PV_TILE_B)
#define PV_SMEM    (3 * PV_STAGE)   // 73728

__global__ __launch_bounds__(128, 2)
void pv_kernel(const float* __restrict__ P, const float* __restrict__ vt,
               float* __restrict__ ctx) {
    extern __shared__ __align__(16) char smem[];
    const int tid  = threadIdx.x;
    const int warp = tid >> 5;
    const int lane = tid & 31;
    const int bh = blockIdx.z;
    const int b  = bh >> 3, h = bh & 7;
    const int m0 = blockIdx.y * 128;

    const float* A = P  + (size_t)bh * NSEQ * NSEQ + (size_t)m0 * NSEQ;
    const float* B = vt + (size_t)bh * DHEAD * NSEQ;

    const int warp_m = warp * 32;
    const int row = lane >> 2, col = lane & 3;
    const int cswz = row * 4;

    float d[2][8][4];
    #pragma unroll
    for (int mt = 0; mt < 2; mt++)
        #pragma unroll
        for (int nt = 0; nt < 8; nt++)
            #pragma unroll
            for (int j = 0; j < 4; j++) d[mt][nt][j] = 0.0f;

    const int nch = NSEQ / 32;   // 8
    load_tile128(A, NSEQ, 0, (float*)smem, tid);
    load_tile64 (B, NSEQ, 0, (float*)(smem + PV_TILE_A), tid);
    CP_COMMIT();
    load_tile128(A, NSEQ, 1, (float*)(smem + PV_STAGE), tid);
    load_tile64 (B, NSEQ, 1, (float*)(smem + PV_STAGE + PV_TILE_A), tid);
    CP_COMMIT();

    for (int c = 0; c < nch; c++) {
        if (c + 1 < nch) CP_WAIT(1);
        else             CP_WAIT(0);
        __syncthreads();

        if (c + 2 < nch) {
            char* st = smem + ((c + 2) % 3) * PV_STAGE;
            load_tile128(A, NSEQ, c + 2, (float*)st, tid);
            load_tile64 (B, NSEQ, c + 2, (float*)(st + PV_TILE_A), tid);
            CP_COMMIT();
        }

        const uint32_t* As = (const uint32_t*)(smem + (c % 3) * PV_STAGE);
        const uint32_t* Bs = (const uint32_t*)(smem + (c % 3) * PV_STAGE + PV_TILE_A);

        #pragma unroll
        for (int ks = 0; ks < 4; ks++) {
            const int koff  = ((ks * 8) | col) ^ cswz;
            const int koff2 = koff ^ 4;

            uint32_t a[2][4];
            #pragma unroll
            for (int mt = 0; mt < 2; mt++) {
                const uint32_t* ap = As + (warp_m + mt * 16 + row) * 32;
                a[mt][0] = ap[koff];
                a[mt][1] = ap[8 * 32 + koff];
                a[mt][2] = ap[koff2];
                a[mt][3] = ap[8 * 32 + koff2];
            }
            uint32_t bfr[8][2];
            #pragma unroll
            for (int nt = 0; nt < 8; nt++) {
                const uint32_t* bp = Bs + (nt * 8 + row) * 32;
                bfr[nt][0] = bp[koff];
                bfr[nt][1] = bp[koff2];
            }
            #pragma unroll
            for (int mt = 0; mt < 2; mt++)
                #pragma unroll
                for (int nt = 0; nt < 8; nt++)
                    mma_tf32(d[mt][nt], a[mt], bfr[nt]);
        }
    }

    // Epilogue: ctx layout [b][q][h*64+d], tf32-rounded
    float* C = ctx + (size_t)b * NSEQ * HDIM + h * DHEAD;
    #pragma unroll
    for (int nt = 0; nt < 8; nt++) {
        const int nb = nt * 8 + col * 2;
        #pragma unroll
        for (int mt = 0; mt < 2; mt++) {
            const int m1 = m0 + warp_m + mt * 16 + row;
            #pragma unroll
            for (int half = 0; half < 2; half++) {
                float* crow = C + (size_t)(m1 + half * 8) * HDIM + nb;
                float v0 = to_tf32(d[mt][nt][half * 2 + 0]);
                float v1 = to_tf32(d[mt][nt][half * 2 + 1]);
                *(float2*)crow = make_float2(v0, v1);
            }
        }
    }
}

// ---------------------------------------------------------------------------
// Weight transpose: dst[n][k] = tf32(src[k][n]), per layer (blockIdx.z)
// ---------------------------------------------------------------------------
__global__ void transpose_kernel(const float* __restrict__ src,
                                 float* __restrict__ dst, int R, int C) {
    __shared__ float t[32][33];
    const size_t lo = (size_t)blockIdx.z * R * C;
    const int c0 = blockIdx.x * 32, r0 = blockIdx.y * 32;
    #pragma unroll
    for (int i = 0; i < 32; i += 8)
        t[threadIdx.y + i][threadIdx.x] =
            src[lo + (size_t)(r0 + threadIdx.y + i) * C + c0 + threadIdx.x];
    __syncthreads();
    #pragma unroll
    for (int i = 0; i < 32; i += 8)
        dst[lo + (size_t)(c0 + threadIdx.y + i) * R + r0 + threadIdx.x] =
            to_tf32(t[threadIdx.x][threadIdx.y + i]);
}

// ---------------------------------------------------------------------------
// LayerNorm: one block (256 threads) per row of 512; exact two-pass, tf32 out
// ---------------------------------------------------------------------------
__global__ void ln_kernel(const float* __restrict__ x,
                          const float* __restrict__ gs,
                          const float* __restrict__ gb,
                          float* __restrict__ y) {
    __shared__ float red[8];
    const int row = blockIdx.x;
    const int tid = threadIdx.x;
    const float* xr = x + (size_t)row * HDIM;

    float v0 = xr[tid];
    float v1 = xr[tid + 256];

    float s = v0 + v1;
    #pragma unroll
    for (int o = 16; o; o >>= 1) s += __shfl_xor_sync(0xffffffffu, s, o);
    if ((tid & 31) == 0) red[tid >> 5] = s;
    __syncthreads();
    if (tid < 8) {
        float t = red[tid];
        #pragma unroll
        for (int o = 4; o; o >>= 1) t += __shfl_xor_sync(0xffu, t, o);
        if (tid == 0) red[0] = t;
    }
    __syncthreads();
    const float mu = red[0] * (1.0f / HDIM);
    __syncthreads();

    const float d0 = v0 - mu, d1 = v1 - mu;
    float sq = d0 * d0 + d1 * d1;
    #pragma unroll
    for (int o = 16; o; o >>= 1) sq += __shfl_xor_sync(0xffffffffu, sq, o);
    if ((tid & 31) == 0) red[tid >> 5] = sq;
    __syncthreads();
    if (tid < 8) {
        float t = red[tid];
        #pragma unroll
        for (int o = 4; o; o >>= 1) t += __shfl_xor_sync(0xffu, t, o);
        if (tid == 0) red[0] = t;
    }
    __syncthreads();
    const float inv = rsqrtf(red[0] * (1.0f / HDIM) + 1e-5f);

    float* yr = y + (size_t)row * HDIM;
    yr[tid]       = to_tf32(d0 * inv * gs[tid]       + gb[tid]);
    yr[tid + 256] = to_tf32(d1 * inv * gs[tid + 256] + gb[tid + 256]);
}

// ---------------------------------------------------------------------------
// Host launcher
// ---------------------------------------------------------------------------
extern "C" void kernel_launch(void* const* d_in, const int* in_sizes, int n_in,
                              void* d_out, int out_size) {
    const float* x_in      = (const float*)d_in[0];
    const float* attn_bias = (const float*)d_in[1];
    const float* ln1_s     = (const float*)d_in[2];
    const float* ln1_b     = (const float*)d_in[3];
    const float* wq        = (const float*)d_in[4];
    const float* bq        = (const float*)d_in[5];
    const float* wk        = (const float*)d_in[6];
    const float* bk        = (const float*)d_in[7];
    const float* wv        = (const float*)d_in[8];
    const float* bv        = (const float*)d_in[9];
    const float* wo        = (const float*)d_in[10];
    const float* bo        = (const float*)d_in[11];
    const float* ln2_s     = (const float*)d_in[12];
    const float* ln2_b     = (const float*)d_in[13];
    const float* w1        = (const float*)d_in[14];
    const float* b1        = (const float*)d_in[15];
    const float* w2        = (const float*)d_in[16];
    const float* b2        = (const float*)d_in[17];

    float* X = (float*)d_out;

    float *yb, *qb, *kb, *vb, *cb, *fb, *sc, *vt;
    float *wqt, *wkt, *wvt, *wot, *w1t, *w2t;
    cudaGetSymbolAddress((void**)&yb, g_y);
    cudaGetSymbolAddress((void**)&qb, g_q);
    cudaGetSymbolAddress((void**)&kb, g_k);
    cudaGetSymbolAddress((void**)&vb, g_v);
    cudaGetSymbolAddress((void**)&cb, g_ctx);
    cudaGetSymbolAddress((void**)&fb, g_ffn);
    cudaGetSymbolAddress((void**)&sc, g_sc);
    cudaGetSymbolAddress((void**)&vt, g_vt);
    cudaGetSymbolAddress((void**)&wqt, g_wqt);
    cudaGetSymbolAddress((void**)&wkt, g_wkt);
    cudaGetSymbolAddress((void**)&wvt, g_wvt);
    cudaGetSymbolAddress((void**)&wot, g_wot);
    cudaGetSymbolAddress((void**)&w1t, g_w1t);
    cudaGetSymbolAddress((void**)&w2t, g_w2t);

    cudaFuncSetAttribute(tgemm_kernel<2>,
                         cudaFuncAttributeMaxDynamicSharedMemorySize, GSMEM3);
    cudaFuncSetAttribute(tgemm_kernel<3>,
                         cudaFuncAttributeMaxDynamicSharedMemorySize, GSMEM3);
    cudaFuncSetAttribute(qkv_kernel,
                         cudaFuncAttributeMaxDynamicSharedMemorySize, GSMEM3);
    cudaFuncSetAttribute(s_gemm_kernel,
                         cudaFuncAttributeMaxDynamicSharedMemorySize, GSMEM3);
    cudaFuncSetAttribute(pv_kernel,
                         cudaFuncAttributeMaxDynamicSharedMemorySize, PV_SMEM);

    cudaMemcpyAsync(X, x_in, (size_t)MROWS * HDIM * sizeof(float),
                    cudaMemcpyDeviceToDevice);

    // One-time weight transposes (+ tf32 rounding)
    {
        const dim3 tb(32, 8);
        const dim3 gHH(HDIM / 32, HDIM / 32, LNUM);
        const dim3 gHF(FDIM / 32, HDIM / 32, LNUM);
        const dim3 gFH(HDIM / 32, FDIM / 32, LNUM);
        transpose_kernel<<<gHH, tb>>>(wq, wqt, HDIM, HDIM);
        transpose_kernel<<<gHH, tb>>>(wk, wkt, HDIM, HDIM);
        transpose_kernel<<<gHH, tb>>>(wv, wvt, HDIM, HDIM);
        transpose_kernel<<<gHH, tb>>>(wo, wot, HDIM, HDIM);
        transpose_kernel<<<gHF, tb>>>(w1, w1t, HDIM, FDIM);
        transpose_kernel<<<gFH, tb>>>(w2, w2t, FDIM, HDIM);
    }

    const dim3 gB(256);
    const dim3 tG(128);
    const dim3 gQKV(12, MROWS / 128);            // (12, 64)
    const dim3 gProj(HDIM / 128, MROWS / 128);   // (4, 64)
    const dim3 gFfn1(FDIM / 128, MROWS / 128);   // (16, 64)
    const dim3 gS(2, 2, NBH);
    const dim3 gPV(1, 2, NBH);
    const dim3 gVt(NSEQ / 32, DHEAD / 32, NBH);
    const dim3 tVt(32, 8);

    for (int l = 0; l < LNUM; l++) {
        const float* wqt_l = wqt + (size_t)l * HDIM * HDIM;
        const float* wkt_l = wkt + (size_t)l * HDIM * HDIM;
        const float* wvt_l = wvt + (size_t)l * HDIM * HDIM;
        const float* wot_l = wot + (size_t)l * HDIM * HDIM;
        const float* w1t_l = w1t + (size_t)l * HDIM * FDIM;
        const float* w2t_l = w2t + (size_t)l * FDIM * HDIM;

        // --- attention block ---
        ln_kernel<<<MROWS, gB>>>(X, ln1_s + l * HDIM, ln1_b + l * HDIM, yb);
        qkv_kernel<<<gQKV, tG, GSMEM3>>>(yb, wqt_l, wkt_l, wvt_l,
                                         bq + l * HDIM, bk + l * HDIM, bv + l * HDIM,
                                         qb, kb, vb);
        s_gemm_kernel<<<gS, tG, GSMEM3>>>(qb, kb, attn_bias, sc);
        softmax_kernel<<<NBH * NSEQ / 8, gB>>>(sc);
        vt_kernel<<<gVt, tVt>>>(vb, vt);
        pv_kernel<<<gPV, tG, PV_SMEM>>>(sc, vt, cb);
        tgemm_kernel<3><<<gProj, tG, GSMEM3>>>(cb, wot_l, bo + l * HDIM, X,
                                               HDIM, HDIM);

        // --- FFN block ---
        ln_kernel<<<MROWS, gB>>>(X, ln2_s + l * HDIM, ln2_b + l * HDIM, yb);
        tgemm_kernel<2><<<gFfn1, tG, GSMEM3>>>(yb, w1t_l, b1 + l * FDIM, fb,
                                               FDIM, HDIM);
        tgemm_kernel<3><<<gProj, tG, GSMEM3>>>(fb, w2t_l, b2 + l * HDIM, X,
                                               HDIM, FDIM);
    }
}

// round 8
// speedup vs baseline: 3.9260x; 1.0329x over previous
#include <cuda_runtime.h>
#include <math.h>
#include <stdint.h>

// Problem constants
#define BSZ    32
#define NSEQ   256
#define HDIM   512
#define NHEADS 8
#define DHEAD  64
#define FDIM   2048
#define LNUM   8
#define MROWS  (BSZ * NSEQ)   // 8192
#define NBH    (BSZ * NHEADS) // 256

// ---------------------------------------------------------------------------
// Scratch (static device globals; no runtime allocation allowed)
// ---------------------------------------------------------------------------
__device__ float g_y  [MROWS * HDIM];
__device__ float g_q  [MROWS * HDIM];
__device__ float g_k  [MROWS * HDIM];
__device__ float g_v  [MROWS * HDIM];
__device__ float g_ctx[MROWS * HDIM];
__device__ float g_ffn[MROWS * FDIM];
__device__ float g_vt [NBH * DHEAD * NSEQ];    // per-head transposed V
// Transposed weights: Wt[n][k] = W[k][n] (tf32-rounded)
__device__ float g_wqt[LNUM * HDIM * HDIM];
__device__ float g_wkt[LNUM * HDIM * HDIM];
__device__ float g_wvt[LNUM * HDIM * HDIM];
__device__ float g_wot[LNUM * HDIM * HDIM];
__device__ float g_w1t[LNUM * HDIM * FDIM];
__device__ float g_w2t[LNUM * FDIM * HDIM];

// ---------------------------------------------------------------------------
// Helpers
// ---------------------------------------------------------------------------
__device__ __forceinline__ float to_tf32(float x) {
    float r;
    asm("cvt.rna.tf32.f32 %0, %1;" : "=f"(r) : "f"(x));
    return r;
}

__device__ __forceinline__ void cp_async16(void* dst, const void* src) {
    uint32_t d;
    asm("{ .reg .u64 t; cvta.to.shared.u64 t, %1; cvt.u32.u64 %0, t; }"
        : "=r"(d) : "l"(dst));
    asm volatile("cp.async.cg.shared.global [%0], [%1], 16;" :: "r"(d), "l"(src));
}

#define CP_COMMIT() asm volatile("cp.async.commit_group;" ::: "memory")
#define CP_WAIT(n)  asm volatile("cp.async.wait_group %0;" :: "n"(n) : "memory")

__device__ __forceinline__ void mma_tf32(float* d, const uint32_t* a, const uint32_t* b) {
    asm volatile(
        "mma.sync.aligned.m16n8k8.row.col.f32.tf32.tf32.f32 "
        "{%0,%1,%2,%3}, {%4,%5,%6,%7}, {%8,%9}, {%0,%1,%2,%3};"
        : "+f"(d[0]), "+f"(d[1]), "+f"(d[2]), "+f"(d[3])
        : "r"(a[0]), "r"(a[1]), "r"(a[2]), "r"(a[3]), "r"(b[0]), "r"(b[1]));
}

// ---------------------------------------------------------------------------
// Tile loaders: rows x 32 k-floats, XOR-swizzled smem
// float (r, k) at r*32 + (k ^ (4*(r&7)))
// ---------------------------------------------------------------------------
__device__ __forceinline__ void load_tile128(const float* __restrict__ base, int lda,
                                             int c, float* sdst, int tid) {
    const float* p = base + c * 32;
    #pragma unroll
    for (int i = 0; i < 8; i++) {
        const int id  = tid + i * 128;
        const int row = id >> 3;
        const int c4  = id & 7;
        const int off = row * 32 + ((c4 * 4) ^ ((row & 7) * 4));
        cp_async16(sdst + off, p + (size_t)row * lda + c4 * 4);
    }
}

// ---------------------------------------------------------------------------
// GEMM core: 128x128 tile, 128 threads (4 warps 2x2, 64x64 each),
// 3-stage cp.async pipeline, single __syncthreads per chunk.
// ---------------------------------------------------------------------------
#define TILE_B    16384
#define STAGE_B   32768
#define GSMEM3    (3 * STAGE_B)    // 98304

__device__ __forceinline__ void gemm_main(const float* __restrict__ A, int lda,
                                          const float* __restrict__ B, int ldb,
                                          int K, char* smem, int tid,
                                          float (&d)[4][8][4]) {
    const int warp   = tid >> 5;
    const int lane   = tid & 31;
    const int warp_m = (warp >> 1) * 64;
    const int warp_n = (warp & 1) * 64;
    const int row    = lane >> 2;
    const int col    = lane & 3;
    const int cswz   = row * 4;

    #pragma unroll
    for (int mt = 0; mt < 4; mt++)
        #pragma unroll
        for (int nt = 0; nt < 8; nt++)
            #pragma unroll
            for (int j = 0; j < 4; j++) d[mt][nt][j] = 0.0f;

    const int nch = K / 32;
    load_tile128(A, lda, 0, (float*)smem, tid);
    load_tile128(B, ldb, 0, (float*)(smem + TILE_B), tid);
    CP_COMMIT();
    load_tile128(A, lda, 1, (float*)(smem + STAGE_B), tid);
    load_tile128(B, ldb, 1, (float*)(smem + STAGE_B + TILE_B), tid);
    CP_COMMIT();

    for (int c = 0; c < nch; c++) {
        if (c + 1 < nch) CP_WAIT(1);
        else             CP_WAIT(0);
        __syncthreads();

        if (c + 2 < nch) {
            char* st = smem + ((c + 2) % 3) * STAGE_B;
            load_tile128(A, lda, c + 2, (float*)st, tid);
            load_tile128(B, ldb, c + 2, (float*)(st + TILE_B), tid);
            CP_COMMIT();
        }

        const uint32_t* As = (const uint32_t*)(smem + (c % 3) * STAGE_B);
        const uint32_t* Bs = (const uint32_t*)(smem + (c % 3) * STAGE_B + TILE_B);

        #pragma unroll
        for (int ks = 0; ks < 4; ks++) {
            const int koff  = ((ks * 8) | col) ^ cswz;
            const int koff2 = koff ^ 4;

            uint32_t a[4][4];
            #pragma unroll
            for (int mt = 0; mt < 4; mt++) {
                const uint32_t* ap = As + (warp_m + mt * 16 + row) * 32;
                a[mt][0] = ap[koff];
                a[mt][1] = ap[8 * 32 + koff];
                a[mt][2] = ap[koff2];
                a[mt][3] = ap[8 * 32 + koff2];
            }
            uint32_t b[8][2];
            #pragma unroll
            for (int nt = 0; nt < 8; nt++) {
                const uint32_t* bp = Bs + (warp_n + nt * 8 + row) * 32;
                b[nt][0] = bp[koff];
                b[nt][1] = bp[koff2];
            }
            #pragma unroll
            for (int mt = 0; mt < 4; mt++)
                #pragma unroll
                for (int nt = 0; nt < 8; nt++)
                    mma_tf32(d[mt][nt], a[mt], b[nt]);
        }
    }
}

// ---------------------------------------------------------------------------
// Generic GEMM kernels (weights pre-transposed)
//   EPI 2: tf32(gelu(acc + bias))        EPI 3: C += acc + bias
// ---------------------------------------------------------------------------
template <int EPI>
__global__ __launch_bounds__(128, 2)
void tgemm_kernel(const float* __restrict__ A, const float* __restrict__ Bt,
                  const float* __restrict__ bias, float* __restrict__ C,
                  int Ncols, int K) {
    extern __shared__ __align__(16) char smem[];
    const int tid  = threadIdx.x;
    const int warp = tid >> 5;
    const int lane = tid & 31;
    const int m0 = blockIdx.y * 128;
    const int n0 = blockIdx.x * 128;

    float d[4][8][4];
    gemm_main(A + (size_t)m0 * K, K, Bt + (size_t)n0 * K, K, K, smem, tid, d);

    const int warp_m = (warp >> 1) * 64;
    const int warp_n = (warp & 1) * 64;
    const int row = lane >> 2, col = lane & 3;

    #pragma unroll
    for (int nt = 0; nt < 8; nt++) {
        const int nb = n0 + warp_n + nt * 8 + col * 2;
        const float2 bv = *(const float2*)(bias + nb);
        #pragma unroll
        for (int mt = 0; mt < 4; mt++) {
            const int m1 = m0 + warp_m + mt * 16 + row;
            #pragma unroll
            for (int half = 0; half < 2; half++) {
                float* crow = C + (size_t)(m1 + half * 8) * Ncols + nb;
                float v0 = d[mt][nt][half * 2 + 0] + bv.x;
                float v1 = d[mt][nt][half * 2 + 1] + bv.y;
                if (EPI == 2) {
                    v0 = to_tf32(0.5f * v0 * (1.0f + erff(v0 * 0.70710678118654752f)));
                    v1 = to_tf32(0.5f * v1 * (1.0f + erff(v1 * 0.70710678118654752f)));
                } else if (EPI == 3) {
                    const float2 old = *(const float2*)crow;
                    v0 += old.x; v1 += old.y;
                }
                *(float2*)crow = make_float2(v0, v1);
            }
        }
    }
}

// ---------------------------------------------------------------------------
// Fused QKV projection: grid.x = 12 -> (sel = x>>2) in {q,k,v}, n0 = (x&3)*128
// ---------------------------------------------------------------------------
__global__ __launch_bounds__(128, 2)
void qkv_kernel(const float* __restrict__ A,
                const float* __restrict__ wqt, const float* __restrict__ wkt,
                const float* __restrict__ wvt,
                const float* __restrict__ bq, const float* __restrict__ bk,
                const float* __restrict__ bv,
                float* __restrict__ q, float* __restrict__ k, float* __restrict__ v) {
    extern __shared__ __align__(16) char smem[];
    const int tid  = threadIdx.x;
    const int warp = tid >> 5;
    const int lane = tid & 31;
    const int sel = blockIdx.x >> 2;
    const int n0  = (blockIdx.x & 3) * 128;
    const int m0  = blockIdx.y * 128;

    const float* Bt   = (sel == 0) ? wqt : (sel == 1) ? wkt : wvt;
    const float* bias = (sel == 0) ? bq  : (sel == 1) ? bk  : bv;
    float*       C    = (sel == 0) ? q   : (sel == 1) ? k   : v;
    const float scale = (sel == 0) ? 0.125f : 1.0f;

    float d[4][8][4];
    gemm_main(A + (size_t)m0 * HDIM, HDIM, Bt + (size_t)n0 * HDIM, HDIM, HDIM,
              smem, tid, d);

    const int warp_m = (warp >> 1) * 64;
    const int warp_n = (warp & 1) * 64;
    const int row = lane >> 2, col = lane & 3;

    #pragma unroll
    for (int nt = 0; nt < 8; nt++) {
        const int nb = n0 + warp_n + nt * 8 + col * 2;
        const float2 bvv = *(const float2*)(bias + nb);
        #pragma unroll
        for (int mt = 0; mt < 4; mt++) {
            const int m1 = m0 + warp_m + mt * 16 + row;
            #pragma unroll
            for (int half = 0; half < 2; half++) {
                float* crow = C + (size_t)(m1 + half * 8) * HDIM + nb;
                float v0 = to_tf32((d[mt][nt][half * 2 + 0] + bvv.x) * scale);
                float v1 = to_tf32((d[mt][nt][half * 2 + 1] + bvv.y) * scale);
                *(float2*)crow = make_float2(v0, v1);
            }
        }
    }
}

// ---------------------------------------------------------------------------
// Per-head V transpose: vt[bh][d][j] = v[b][j][h*64+d]
// ---------------------------------------------------------------------------
__global__ void vt_kernel(const float* __restrict__ v, float* __restrict__ vt) {
    __shared__ float t[32][33];
    const int bh = blockIdx.z;
    const int b  = bh >> 3, h = bh & 7;
    const int j0 = blockIdx.x * 32;
    const int d0 = blockIdx.y * 32;
    const float* src = v + (size_t)b * NSEQ * HDIM + h * DHEAD;
    float* dst = vt + (size_t)bh * DHEAD * NSEQ;
    #pragma unroll
    for (int i = 0; i < 32; i += 8)
        t[threadIdx.y + i][threadIdx.x] =
            src[(size_t)(j0 + threadIdx.y + i) * HDIM + d0 + threadIdx.x];
    __syncthreads();
    #pragma unroll
    for (int i = 0; i < 32; i += 8)
        dst[(size_t)(d0 + threadIdx.y + i) * NSEQ + j0 + threadIdx.x] =
            t[threadIdx.x][threadIdx.y + i];
}

// ---------------------------------------------------------------------------
// Fused flash attention: ctx = softmax(Q·K^T + bias) · V
// Grid (2 q-tiles, 256 bh), 256 threads (8 warps x 16 q-rows).
// Q staged once (fragments -> regs), region reused as per-warp P buffer.
// 4 key-chunks of 64, double-buffered K/V via cp.async, online softmax.
// smem: [0,32K) Q then P; [32K,64K) stage0 (K 16K | V 16K); [64K,96K) stage1.
// ---------------------------------------------------------------------------
#define FA_SMEM (32768 + 2 * 32768)   // 98304

__device__ __forceinline__ void load_kv(const float* __restrict__ Kb,
                                        const float* __restrict__ Vb,
                                        int j0, char* st, int tid) {
    float* Ks = (float*)st;
    float* Vs = (float*)(st + 16384);
    #pragma unroll
    for (int i = 0; i < 4; i++) {
        const int id   = tid + i * 256;     // 0..1023
        const int tile = id >> 9;
        const int r    = (id >> 3) & 63;
        const int c4   = id & 7;
        const int off  = tile * 2048 + r * 32 + ((c4 * 4) ^ ((r & 7) * 4));
        cp_async16(Ks + off, Kb + (size_t)(j0 + r) * HDIM + tile * 32 + c4 * 4);
        cp_async16(Vs + off, Vb + (size_t)r * NSEQ + j0 + tile * 32 + c4 * 4);
    }
}

__global__ __launch_bounds__(256)
void fattn_kernel(const float* __restrict__ q, const float* __restrict__ k,
                  const float* __restrict__ vt, const float* __restrict__ attn_bias,
                  float* __restrict__ ctx) {
    extern __shared__ __align__(16) char smem[];
    float* QP   = (float*)smem;
    char* stage = smem + 32768;

    const int tid  = threadIdx.x;
    const int warp = tid >> 5;
    const int lane = tid & 31;
    const int row  = lane >> 2;
    const int col  = lane & 3;
    const int bh = blockIdx.y;
    const int b  = bh >> 3, h = bh & 7;
    const int m0 = blockIdx.x * 128;

    const float* Qb = q  + (size_t)b * NSEQ * HDIM + (size_t)m0 * HDIM + h * DHEAD;
    const float* Kb = k  + (size_t)b * NSEQ * HDIM + h * DHEAD;
    const float* Vb = vt + (size_t)bh * DHEAD * NSEQ;

    // Stage Q: 128x64 as two 128x32 swizzled tiles
    #pragma unroll
    for (int i = 0; i < 8; i++) {
        const int id   = tid + i * 256;     // 0..2047
        const int tile = id >> 10;
        const int r    = (id >> 3) & 127;
        const int c4   = id & 7;
        const int off  = tile * 4096 + r * 32 + ((c4 * 4) ^ ((r & 7) * 4));
        cp_async16(QP + off, Qb + (size_t)r * HDIM + tile * 32 + c4 * 4);
    }
    CP_COMMIT();
    load_kv(Kb, Vb, 0, stage, tid);
    CP_COMMIT();

    // Wait for Q (KV0 may still be in flight), extract Q fragments
    CP_WAIT(1);
    __syncthreads();
    uint32_t aq[8][4];
    {
        const uint32_t* Qs = (const uint32_t*)QP;
        #pragma unroll
        for (int kc = 0; kc < 8; kc++) {
            const int koff = ((kc & 3) * 8 + col) ^ (row * 4);
            const uint32_t* ap = Qs + (kc >> 2) * 4096 + (warp * 16 + row) * 32;
            aq[kc][0] = ap[koff];
            aq[kc][1] = ap[256 + koff];
            aq[kc][2] = ap[koff ^ 4];
            aq[kc][3] = ap[256 + (koff ^ 4)];
        }
    }
    __syncthreads();   // Q region now reusable as P buffer

    float m0r = -1e30f, m1r = -1e30f, l0 = 0.0f, l1 = 0.0f;
    float cacc[8][4];
    #pragma unroll
    for (int nt = 0; nt < 8; nt++)
        #pragma unroll
        for (int j = 0; j < 4; j++) cacc[nt][j] = 0.0f;

    const float* bias_b = attn_bias + (size_t)bh * NSEQ * NSEQ
                        + (size_t)(m0 + warp * 16 + row) * NSEQ;

    for (int c = 0; c < 4; c++) {
        CP_WAIT(0);
        __syncthreads();
        if (c < 3) {
            load_kv(Kb, Vb, (c + 1) * 64, stage + ((c + 1) & 1) * 32768, tid);
            CP_COMMIT();
        }

        const uint32_t* Ks = (const uint32_t*)(stage + (c & 1) * 32768);
        const uint32_t* Vs = Ks + 4096;

        // S = Q · K^T over this 64-key chunk
        float s[8][4];
        #pragma unroll
        for (int nt = 0; nt < 8; nt++)
            #pragma unroll
            for (int j = 0; j < 4; j++) s[nt][j] = 0.0f;

        #pragma unroll
        for (int kc = 0; kc < 8; kc++) {
            const int koff = ((kc & 3) * 8 + col) ^ (row * 4);
            const uint32_t* kt = Ks + (kc >> 2) * 2048;
            uint32_t bfr[8][2];
            #pragma unroll
            for (int nt = 0; nt < 8; nt++) {
                const uint32_t* bp = kt + (nt * 8 + row) * 32;
                bfr[nt][0] = bp[koff];
                bfr[nt][1] = bp[koff ^ 4];
            }
            #pragma unroll
            for (int nt = 0; nt < 8; nt++)
                mma_tf32(s[nt], aq[kc], bfr[nt]);
        }

        // + bias, chunk row-max
        float mx0 = -1e30f, mx1 = -1e30f;
        #pragma unroll
        for (int nt = 0; nt < 8; nt++) {
            const float* bp = bias_b + c * 64 + nt * 8 + 2 * col;
            const float2 b0 = *(const float2*)bp;
            const float2 b1 = *(const float2*)(bp + 8 * NSEQ);
            s[nt][0] += b0.x; s[nt][1] += b0.y;
            s[nt][2] += b1.x; s[nt][3] += b1.y;
            mx0 = fmaxf(mx0, fmaxf(s[nt][0], s[nt][1]));
            mx1 = fmaxf(mx1, fmaxf(s[nt][2], s[nt][3]));
        }
        mx0 = fmaxf(mx0, __shfl_xor_sync(0xffffffffu, mx0, 1));
        mx0 = fmaxf(mx0, __shfl_xor_sync(0xffffffffu, mx0, 2));
        mx1 = fmaxf(mx1, __shfl_xor_sync(0xffffffffu, mx1, 1));
        mx1 = fmaxf(mx1, __shfl_xor_sync(0xffffffffu, mx1, 2));

        const float mn0 = fmaxf(m0r, mx0);
        const float mn1 = fmaxf(m1r, mx1);
        const float f0 = __expf(m0r - mn0);
        const float f1 = __expf(m1r - mn1);
        m0r = mn0; m1r = mn1;

        float sum0 = 0.0f, sum1 = 0.0f;
        #pragma unroll
        for (int nt = 0; nt < 8; nt++) {
            s[nt][0] = __expf(s[nt][0] - mn0);
            s[nt][1] = __expf(s[nt][1] - mn0);
            s[nt][2] = __expf(s[nt][2] - mn1);
            s[nt][3] = __expf(s[nt][3] - mn1);
            sum0 += s[nt][0] + s[nt][1];
            sum1 += s[nt][2] + s[nt][3];
        }
        l0 = l0 * f0 + sum0;
        l1 = l1 * f1 + sum1;
        #pragma unroll
        for (int nt = 0; nt < 8; nt++) {
            cacc[nt][0] *= f0; cacc[nt][1] *= f0;
            cacc[nt][2] *= f1; cacc[nt][3] *= f1;
        }

        // Store P tile (warp-private, swizzled 2x 16x32)
        float* Pw = QP + warp * 1024;
        #pragma unroll
        for (int nt = 0; nt < 8; nt++) {
            const int c32 = (nt & 3) * 8 + 2 * col;
            float* pt = Pw + (nt >> 2) * 512;
            *(float2*)(pt + row * 32 + (c32 ^ (row * 4))) =
                make_float2(to_tf32(s[nt][0]), to_tf32(s[nt][1]));
            *(float2*)(pt + (row + 8) * 32 + (c32 ^ (row * 4))) =
                make_float2(to_tf32(s[nt][2]), to_tf32(s[nt][3]));
        }
        __syncwarp();

        // ctx += P · V
        const uint32_t* Pr = (const uint32_t*)QP + warp * 1024;
        #pragma unroll
        for (int kc = 0; kc < 8; kc++) {
            const int koff = ((kc & 3) * 8 + col) ^ (row * 4);
            const uint32_t* pt = Pr + (kc >> 2) * 512 + row * 32;
            uint32_t a[4];
            a[0] = pt[koff];
            a[1] = pt[256 + koff];
            a[2] = pt[koff ^ 4];
            a[3] = pt[256 + (koff ^ 4)];
            const uint32_t* vtile = Vs + (kc >> 2) * 2048;
            uint32_t bfr[8][2];
            #pragma unroll
            for (int nt = 0; nt < 8; nt++) {
                const uint32_t* bp = vtile + (nt * 8 + row) * 32;
                bfr[nt][0] = bp[koff];
                bfr[nt][1] = bp[koff ^ 4];
            }
            #pragma unroll
            for (int nt = 0; nt < 8; nt++)
                mma_tf32(cacc[nt], a, bfr[nt]);
        }
    }

    // Final normalize + write ctx [b][q][h*64+d], tf32-rounded
    l0 += __shfl_xor_sync(0xffffffffu, l0, 1);
    l0 += __shfl_xor_sync(0xffffffffu, l0, 2);
    l1 += __shfl_xor_sync(0xffffffffu, l1, 1);
    l1 += __shfl_xor_sync(0xffffffffu, l1, 2);
    const float inv0 = 1.0f / l0;
    const float inv1 = 1.0f / l1;

    float* Cb = ctx + (size_t)b * NSEQ * HDIM + h * DHEAD
              + (size_t)(m0 + warp * 16 + row) * HDIM;
    #pragma unroll
    for (int nt = 0; nt < 8; nt++) {
        const int nb = nt * 8 + 2 * col;
        *(float2*)(Cb + nb) =
            make_float2(to_tf32(cacc[nt][0] * inv0), to_tf32(cacc[nt][1] * inv0));
        *(float2*)(Cb + 8 * HDIM + nb) =
            make_float2(to_tf32(cacc[nt][2] * inv1), to_tf32(cacc[nt][3] * inv1));
    }
}

// ---------------------------------------------------------------------------
// Weight transpose: dst[n][k] = tf32(src[k][n]), per layer (blockIdx.z)
// ---------------------------------------------------------------------------
__global__ void transpose_kernel(const float* __restrict__ src,
                                 float* __restrict__ dst, int R, int C) {
    __shared__ float t[32][33];
    const size_t lo = (size_t)blockIdx.z * R * C;
    const int c0 = blockIdx.x * 32, r0 = blockIdx.y * 32;
    #pragma unroll
    for (int i = 0; i < 32; i += 8)
        t[threadIdx.y + i][threadIdx.x] =
            src[lo + (size_t)(r0 + threadIdx.y + i) * C + c0 + threadIdx.x];
    __syncthreads();
    #pragma unroll
    for (int i = 0; i < 32; i += 8)
        dst[lo + (size_t)(c0 + threadIdx.y + i) * R + r0 + threadIdx.x] =
            to_tf32(t[threadIdx.x][threadIdx.y + i]);
}

// ---------------------------------------------------------------------------
// LayerNorm: one block (256 threads) per row of 512; exact two-pass, tf32 out
// ---------------------------------------------------------------------------
__global__ void ln_kernel(const float* __restrict__ x,
                          const float* __restrict__ gs,
                          const float* __restrict__ gb,
                          float* __restrict__ y) {
    __shared__ float red[8];
    const int row = blockIdx.x;
    const int tid = threadIdx.x;
    const float* xr = x + (size_t)row * HDIM;

    float v0 = xr[tid];
    float v1 = xr[tid + 256];

    float s = v0 + v1;
    #pragma unroll
    for (int o = 16; o; o >>= 1) s += __shfl_xor_sync(0xffffffffu, s, o);
    if ((tid & 31) == 0) red[tid >> 5] = s;
    __syncthreads();
    if (tid < 8) {
        float t = red[tid];
        #pragma unroll
        for (int o = 4; o; o >>= 1) t += __shfl_xor_sync(0xffu, t, o);
        if (tid == 0) red[0] = t;
    }
    __syncthreads();
    const float mu = red[0] * (1.0f / HDIM);
    __syncthreads();

    const float d0 = v0 - mu, d1 = v1 - mu;
    float sq = d0 * d0 + d1 * d1;
    #pragma unroll
    for (int o = 16; o; o >>= 1) sq += __shfl_xor_sync(0xffffffffu, sq, o);
    if ((tid & 31) == 0) red[tid >> 5] = sq;
    __syncthreads();
    if (tid < 8) {
        float t = red[tid];
        #pragma unroll
        for (int o = 4; o; o >>= 1) t += __shfl_xor_sync(0xffu, t, o);
        if (tid == 0) red[0] = t;
    }
    __syncthreads();
    const float inv = rsqrtf(red[0] * (1.0f / HDIM) + 1e-5f);

    float* yr = y + (size_t)row * HDIM;
    yr[tid]       = to_tf32(d0 * inv * gs[tid]       + gb[tid]);
    yr[tid + 256] = to_tf32(d1 * inv * gs[tid + 256] + gb[tid + 256]);
}

// ---------------------------------------------------------------------------
// Host launcher
// ---------------------------------------------------------------------------
extern "C" void kernel_launch(void* const* d_in, const int* in_sizes, int n_in,
                              void* d_out, int out_size) {
    const float* x_in      = (const float*)d_in[0];
    const float* attn_bias = (const float*)d_in[1];
    const float* ln1_s     = (const float*)d_in[2];
    const float* ln1_b     = (const float*)d_in[3];
    const float* wq        = (const float*)d_in[4];
    const float* bq        = (const float*)d_in[5];
    const float* wk        = (const float*)d_in[6];
    const float* bk        = (const float*)d_in[7];
    const float* wv        = (const float*)d_in[8];
    const float* bv        = (const float*)d_in[9];
    const float* wo        = (const float*)d_in[10];
    const float* bo        = (const float*)d_in[11];
    const float* ln2_s     = (const float*)d_in[12];
    const float* ln2_b     = (const float*)d_in[13];
    const float* w1        = (const float*)d_in[14];
    const float* b1        = (const float*)d_in[15];
    const float* w2        = (const float*)d_in[16];
    const float* b2        = (const float*)d_in[17];

    float* X = (float*)d_out;

    float *yb, *qb, *kb, *vb, *cb, *fb, *vt;
    float *wqt, *wkt, *wvt, *wot, *w1t, *w2t;
    cudaGetSymbolAddress((void**)&yb, g_y);
    cudaGetSymbolAddress((void**)&qb, g_q);
    cudaGetSymbolAddress((void**)&kb, g_k);
    cudaGetSymbolAddress((void**)&vb, g_v);
    cudaGetSymbolAddress((void**)&cb, g_ctx);
    cudaGetSymbolAddress((void**)&fb, g_ffn);
    cudaGetSymbolAddress((void**)&vt, g_vt);
    cudaGetSymbolAddress((void**)&wqt, g_wqt);
    cudaGetSymbolAddress((void**)&wkt, g_wkt);
    cudaGetSymbolAddress((void**)&wvt, g_wvt);
    cudaGetSymbolAddress((void**)&wot, g_wot);
    cudaGetSymbolAddress((void**)&w1t, g_w1t);
    cudaGetSymbolAddress((void**)&w2t, g_w2t);

    cudaFuncSetAttribute(tgemm_kernel<2>,
                         cudaFuncAttributeMaxDynamicSharedMemorySize, GSMEM3);
    cudaFuncSetAttribute(tgemm_kernel<3>,
                         cudaFuncAttributeMaxDynamicSharedMemorySize, GSMEM3);
    cudaFuncSetAttribute(qkv_kernel,
                         cudaFuncAttributeMaxDynamicSharedMemorySize, GSMEM3);
    cudaFuncSetAttribute(fattn_kernel,
                         cudaFuncAttributeMaxDynamicSharedMemorySize, FA_SMEM);

    cudaMemcpyAsync(X, x_in, (size_t)MROWS * HDIM * sizeof(float),
                    cudaMemcpyDeviceToDevice);

    // One-time weight transposes (+ tf32 rounding)
    {
        const dim3 tb(32, 8);
        const dim3 gHH(HDIM / 32, HDIM / 32, LNUM);
        const dim3 gHF(FDIM / 32, HDIM / 32, LNUM);
        const dim3 gFH(HDIM / 32, FDIM / 32, LNUM);
        transpose_kernel<<<gHH, tb>>>(wq, wqt, HDIM, HDIM);
        transpose_kernel<<<gHH, tb>>>(wk, wkt, HDIM, HDIM);
        transpose_kernel<<<gHH, tb>>>(wv, wvt, HDIM, HDIM);
        transpose_kernel<<<gHH, tb>>>(wo, wot, HDIM, HDIM);
        transpose_kernel<<<gHF, tb>>>(w1, w1t, HDIM, FDIM);
        transpose_kernel<<<gFH, tb>>>(w2, w2t, FDIM, HDIM);
    }

    const dim3 gB(256);
    const dim3 tG(128);
    const dim3 gQKV(12, MROWS / 128);            // (12, 64)
    const dim3 gProj(HDIM / 128, MROWS / 128);   // (4, 64)
    const dim3 gFfn1(FDIM / 128, MROWS / 128);   // (16, 64)
    const dim3 gFA(NSEQ / 128, NBH);             // (2, 256)
    const dim3 gVt(NSEQ / 32, DHEAD / 32, NBH);
    const dim3 tVt(32, 8);

    for (int l = 0; l < LNUM; l++) {
        const float* wqt_l = wqt + (size_t)l * HDIM * HDIM;
        const float* wkt_l = wkt + (size_t)l * HDIM * HDIM;
        const float* wvt_l = wvt + (size_t)l * HDIM * HDIM;
        const float* wot_l = wot + (size_t)l * HDIM * HDIM;
        const float* w1t_l = w1t + (size_t)l * HDIM * FDIM;
        const float* w2t_l = w2t + (size_t)l * FDIM * HDIM;

        // --- attention block ---
        ln_kernel<<<MROWS, gB>>>(X, ln1_s + l * HDIM, ln1_b + l * HDIM, yb);
        qkv_kernel<<<gQKV, tG, GSMEM3>>>(yb, wqt_l, wkt_l, wvt_l,
                                         bq + l * HDIM, bk + l * HDIM, bv + l * HDIM,
                                         qb, kb, vb);
        vt_kernel<<<gVt, tVt>>>(vb, vt);
        fattn_kernel<<<gFA, gB, FA_SMEM>>>(qb, kb, vt, attn_bias, cb);
        tgemm_kernel<3><<<gProj, tG, GSMEM3>>>(cb, wot_l, bo + l * HDIM, X,
                                               HDIM, HDIM);

        // --- FFN block ---
        ln_kernel<<<MROWS, gB>>>(X, ln2_s + l * HDIM, ln2_b + l * HDIM, yb);
        tgemm_kernel<2><<<gFfn1, tG, GSMEM3>>>(yb, w1t_l, b1 + l * FDIM, fb,
                                               FDIM, HDIM);
        tgemm_kernel<3><<<gProj, tG, GSMEM3>>>(fb, w2t_l, b2 + l * HDIM, X,
                                               HDIM, FDIM);
    }
}

// round 9
// speedup vs baseline: 6.0494x; 1.5409x over previous
#include <cuda_runtime.h>
#include <cuda_fp16.h>
#include <math.h>
#include <stdint.h>

// Problem constants
#define BSZ    32
#define NSEQ   256
#define HDIM   512
#define NHEADS 8
#define DHEAD  64
#define FDIM   2048
#define LNUM   8
#define MROWS  (BSZ * NSEQ)   // 8192
#define NBH    (BSZ * NHEADS) // 256

// ---------------------------------------------------------------------------
// Scratch (static device globals; no runtime allocation allowed)
// Activations in fp16; residual stream stays fp32 in d_out.
// ---------------------------------------------------------------------------
__device__ __half g_y  [MROWS * HDIM];
__device__ __half g_q  [MROWS * HDIM];
__device__ __half g_k  [MROWS * HDIM];
__device__ __half g_v  [MROWS * HDIM];
__device__ __half g_ctx[MROWS * HDIM];
__device__ __half g_ffn[MROWS * FDIM];
__device__ __half g_vt [NBH * DHEAD * NSEQ];    // per-head transposed V
// Transposed weights: Wt[n][k] = half(W[k][n])
__device__ __half g_wqt[LNUM * HDIM * HDIM];
__device__ __half g_wkt[LNUM * HDIM * HDIM];
__device__ __half g_wvt[LNUM * HDIM * HDIM];
__device__ __half g_wot[LNUM * HDIM * HDIM];
__device__ __half g_w1t[LNUM * HDIM * FDIM];
__device__ __half g_w2t[LNUM * FDIM * HDIM];

// ---------------------------------------------------------------------------
// Helpers
// ---------------------------------------------------------------------------
__device__ __forceinline__ void cp_async16(void* dst, const void* src) {
    uint32_t d;
    asm("{ .reg .u64 t; cvta.to.shared.u64 t, %1; cvt.u32.u64 %0, t; }"
        : "=r"(d) : "l"(dst));
    asm volatile("cp.async.cg.shared.global [%0], [%1], 16;" :: "r"(d), "l"(src));
}

#define CP_COMMIT() asm volatile("cp.async.commit_group;" ::: "memory")
#define CP_WAIT(n)  asm volatile("cp.async.wait_group %0;" :: "n"(n) : "memory")

// fp16 MMA m16n8k16, fp32 accumulate
__device__ __forceinline__ void mma_f16(float* d, const uint32_t* a, const uint32_t* b) {
    asm volatile(
        "mma.sync.aligned.m16n8k16.row.col.f32.f16.f16.f32 "
        "{%0,%1,%2,%3}, {%4,%5,%6,%7}, {%8,%9}, {%0,%1,%2,%3};"
        : "+f"(d[0]), "+f"(d[1]), "+f"(d[2]), "+f"(d[3])
        : "r"(a[0]), "r"(a[1]), "r"(a[2]), "r"(a[3]), "r"(b[0]), "r"(b[1]));
}

// ---------------------------------------------------------------------------
// fp16 tile loader: 128 rows x 64 halves (128 B/row), swizzled 16B chunks:
// chunk ck of row r lands at r*128 + ((ck ^ (r&7)) * 16)
// ---------------------------------------------------------------------------
__device__ __forceinline__ void load_tile128h(const __half* __restrict__ base, int lda,
                                              int c, char* sdst, int tid) {
    const __half* p = base + c * 64;
    #pragma unroll
    for (int i = 0; i < 8; i++) {
        const int id  = tid + i * 128;
        const int row = id >> 3;
        const int ck  = id & 7;
        const int off = row * 128 + ((ck ^ (row & 7)) * 16);
        cp_async16(sdst + off, p + (size_t)row * lda + ck * 8);
    }
}

// ---------------------------------------------------------------------------
// GEMM core: 128x128 tile, BK=64 halves, 128 threads (4 warps 2x2, 64x64),
// 3-stage cp.async pipeline, single __syncthreads per chunk.
// ---------------------------------------------------------------------------
#define TILE_B    16384                 // 128 x 64 halves
#define STAGE_B   32768
#define GSMEM3    (3 * STAGE_B)         // 98304

__device__ __forceinline__ void gemm_main_h(const __half* __restrict__ A, int lda,
                                            const __half* __restrict__ B, int ldb,
                                            int K, char* smem, int tid,
                                            float (&d)[4][8][4]) {
    const int warp   = tid >> 5;
    const int lane   = tid & 31;
    const int warp_m = (warp >> 1) * 64;
    const int warp_n = (warp & 1) * 64;
    const int row    = lane >> 2;
    const int col    = lane & 3;

    #pragma unroll
    for (int mt = 0; mt < 4; mt++)
        #pragma unroll
        for (int nt = 0; nt < 8; nt++)
            #pragma unroll
            for (int j = 0; j < 4; j++) d[mt][nt][j] = 0.0f;

    const int nch = K / 64;
    load_tile128h(A, lda, 0, smem, tid);
    load_tile128h(B, ldb, 0, smem + TILE_B, tid);
    CP_COMMIT();
    load_tile128h(A, lda, 1, smem + STAGE_B, tid);
    load_tile128h(B, ldb, 1, smem + STAGE_B + TILE_B, tid);
    CP_COMMIT();

    for (int c = 0; c < nch; c++) {
        if (c + 1 < nch) CP_WAIT(1);
        else             CP_WAIT(0);
        __syncthreads();

        if (c + 2 < nch) {
            char* st = smem + ((c + 2) % 3) * STAGE_B;
            load_tile128h(A, lda, c + 2, st, tid);
            load_tile128h(B, ldb, c + 2, st + TILE_B, tid);
            CP_COMMIT();
        }

        const char* Asb = smem + (c % 3) * STAGE_B;
        const char* Bsb = Asb + TILE_B;

        #pragma unroll
        for (int ks = 0; ks < 4; ks++) {
            const int ck   = ks * 2;
            const int swz0 = ((ck ^ (row & 7)) * 16) + 4 * col;
            const int swz1 = (((ck + 1) ^ (row & 7)) * 16) + 4 * col;

            uint32_t a[4][4];
            #pragma unroll
            for (int mt = 0; mt < 4; mt++) {
                const char* ap0 = Asb + (warp_m + mt * 16 + row) * 128;
                const char* ap8 = ap0 + 8 * 128;
                a[mt][0] = *(const uint32_t*)(ap0 + swz0);
                a[mt][1] = *(const uint32_t*)(ap8 + swz0);
                a[mt][2] = *(const uint32_t*)(ap0 + swz1);
                a[mt][3] = *(const uint32_t*)(ap8 + swz1);
            }
            uint32_t b[8][2];
            #pragma unroll
            for (int nt = 0; nt < 8; nt++) {
                const char* bp = Bsb + (warp_n + nt * 8 + row) * 128;
                b[nt][0] = *(const uint32_t*)(bp + swz0);
                b[nt][1] = *(const uint32_t*)(bp + swz1);
            }
            #pragma unroll
            for (int mt = 0; mt < 4; mt++)
                #pragma unroll
                for (int nt = 0; nt < 8; nt++)
                    mma_f16(d[mt][nt], a[mt], b[nt]);
        }
    }
}

// ---------------------------------------------------------------------------
// Generic GEMM kernels (fp16 in, weights pre-transposed)
//   EPI 2: half(gelu(acc + bias)) -> half C   EPI 3: fp32 C += acc + bias
// ---------------------------------------------------------------------------
template <int EPI>
__global__ __launch_bounds__(128, 2)
void tgemm_kernel(const __half* __restrict__ A, const __half* __restrict__ Bt,
                  const float* __restrict__ bias, void* __restrict__ Cv,
                  int Ncols, int K) {
    extern __shared__ __align__(16) char smem[];
    const int tid  = threadIdx.x;
    const int warp = tid >> 5;
    const int lane = tid & 31;
    const int m0 = blockIdx.y * 128;
    const int n0 = blockIdx.x * 128;

    float d[4][8][4];
    gemm_main_h(A + (size_t)m0 * K, K, Bt + (size_t)n0 * K, K, K, smem, tid, d);

    const int warp_m = (warp >> 1) * 64;
    const int warp_n = (warp & 1) * 64;
    const int row = lane >> 2, col = lane & 3;

    #pragma unroll
    for (int nt = 0; nt < 8; nt++) {
        const int nb = n0 + warp_n + nt * 8 + col * 2;
        const float2 bv = *(const float2*)(bias + nb);
        #pragma unroll
        for (int mt = 0; mt < 4; mt++) {
            const int m1 = m0 + warp_m + mt * 16 + row;
            #pragma unroll
            for (int half_i = 0; half_i < 2; half_i++) {
                const int mr = m1 + half_i * 8;
                float v0 = d[mt][nt][half_i * 2 + 0] + bv.x;
                float v1 = d[mt][nt][half_i * 2 + 1] + bv.y;
                if (EPI == 2) {
                    v0 = 0.5f * v0 * (1.0f + erff(v0 * 0.70710678118654752f));
                    v1 = 0.5f * v1 * (1.0f + erff(v1 * 0.70710678118654752f));
                    __half* crow = (__half*)Cv + (size_t)mr * Ncols + nb;
                    *(__half2*)crow = __floats2half2_rn(v0, v1);
                } else {
                    float* crow = (float*)Cv + (size_t)mr * Ncols + nb;
                    const float2 old = *(const float2*)crow;
                    *(float2*)crow = make_float2(v0 + old.x, v1 + old.y);
                }
            }
        }
    }
}

// ---------------------------------------------------------------------------
// Fused QKV projection: grid.x = 12 -> (sel = x>>2) in {q,k,v}, n0 = (x&3)*128
// ---------------------------------------------------------------------------
__global__ __launch_bounds__(128, 2)
void qkv_kernel(const __half* __restrict__ A,
                const __half* __restrict__ wqt, const __half* __restrict__ wkt,
                const __half* __restrict__ wvt,
                const float* __restrict__ bq, const float* __restrict__ bk,
                const float* __restrict__ bv,
                __half* __restrict__ q, __half* __restrict__ k, __half* __restrict__ v) {
    extern __shared__ __align__(16) char smem[];
    const int tid  = threadIdx.x;
    const int warp = tid >> 5;
    const int lane = tid & 31;
    const int sel = blockIdx.x >> 2;
    const int n0  = (blockIdx.x & 3) * 128;
    const int m0  = blockIdx.y * 128;

    const __half* Bt  = (sel == 0) ? wqt : (sel == 1) ? wkt : wvt;
    const float* bias = (sel == 0) ? bq  : (sel == 1) ? bk  : bv;
    __half*      C    = (sel == 0) ? q   : (sel == 1) ? k   : v;
    const float scale = (sel == 0) ? 0.125f : 1.0f;

    float d[4][8][4];
    gemm_main_h(A + (size_t)m0 * HDIM, HDIM, Bt + (size_t)n0 * HDIM, HDIM, HDIM,
                smem, tid, d);

    const int warp_m = (warp >> 1) * 64;
    const int warp_n = (warp & 1) * 64;
    const int row = lane >> 2, col = lane & 3;

    #pragma unroll
    for (int nt = 0; nt < 8; nt++) {
        const int nb = n0 + warp_n + nt * 8 + col * 2;
        const float2 bvv = *(const float2*)(bias + nb);
        #pragma unroll
        for (int mt = 0; mt < 4; mt++) {
            const int m1 = m0 + warp_m + mt * 16 + row;
            #pragma unroll
            for (int half_i = 0; half_i < 2; half_i++) {
                __half* crow = C + (size_t)(m1 + half_i * 8) * HDIM + nb;
                const float v0 = (d[mt][nt][half_i * 2 + 0] + bvv.x) * scale;
                const float v1 = (d[mt][nt][half_i * 2 + 1] + bvv.y) * scale;
                *(__half2*)crow = __floats2half2_rn(v0, v1);
            }
        }
    }
}

// ---------------------------------------------------------------------------
// Per-head V transpose: vt[bh][d][j] = v[b][j][h*64+d] (fp16)
// ---------------------------------------------------------------------------
__global__ void vt_kernel(const __half* __restrict__ v, __half* __restrict__ vt) {
    __shared__ __half t[32][33];
    const int bh = blockIdx.z;
    const int b  = bh >> 3, h = bh & 7;
    const int j0 = blockIdx.x * 32;
    const int d0 = blockIdx.y * 32;
    const __half* src = v + (size_t)b * NSEQ * HDIM + h * DHEAD;
    __half* dst = vt + (size_t)bh * DHEAD * NSEQ;
    #pragma unroll
    for (int i = 0; i < 32; i += 8)
        t[threadIdx.y + i][threadIdx.x] =
            src[(size_t)(j0 + threadIdx.y + i) * HDIM + d0 + threadIdx.x];
    __syncthreads();
    #pragma unroll
    for (int i = 0; i < 32; i += 8)
        dst[(size_t)(d0 + threadIdx.y + i) * NSEQ + j0 + threadIdx.x] =
            t[threadIdx.x][threadIdx.y + i];
}

// ---------------------------------------------------------------------------
// Fused flash attention (fp16 operands): ctx = softmax(Q·K^T + bias) · V
// Grid (2 q-tiles, 256 bh), 256 threads (8 warps x 16 q-rows).
// smem: [0,16K) Q (then per-warp P); [16K,32K) stage0 (K 8K | V 8K); [32K,48K) stage1
// ---------------------------------------------------------------------------
#define FA_STAGE 16384
#define FA_SMEM  (16384 + 2 * FA_STAGE)   // 49152

__device__ __forceinline__ void load_kv_h(const __half* __restrict__ Kb,
                                          const __half* __restrict__ Vb,
                                          int j0, char* st, int tid) {
    char* Ks = st;
    char* Vs = st + 8192;
    #pragma unroll
    for (int i = 0; i < 2; i++) {
        const int id = tid + i * 256;     // 0..511
        const int r  = id >> 3;           // 0..63
        const int ck = id & 7;
        const int off = r * 128 + ((ck ^ (r & 7)) * 16);
        cp_async16(Ks + off, Kb + (size_t)(j0 + r) * HDIM + ck * 8);
        cp_async16(Vs + off, Vb + (size_t)r * NSEQ + j0 + ck * 8);
    }
}

__global__ __launch_bounds__(256, 2)
void fattn_kernel(const __half* __restrict__ q, const __half* __restrict__ k,
                  const __half* __restrict__ vt, const float* __restrict__ attn_bias,
                  __half* __restrict__ ctx) {
    extern __shared__ __align__(16) char smem[];
    char* QP    = smem;            // 128 rows x 128 B  (Q, later P)
    char* stage = smem + 16384;

    const int tid  = threadIdx.x;
    const int warp = tid >> 5;
    const int lane = tid & 31;
    const int row  = lane >> 2;
    const int col  = lane & 3;
    const int bh = blockIdx.y;
    const int b  = bh >> 3, h = bh & 7;
    const int m0 = blockIdx.x * 128;

    const __half* Qb = q  + (size_t)b * NSEQ * HDIM + (size_t)m0 * HDIM + h * DHEAD;
    const __half* Kb = k  + (size_t)b * NSEQ * HDIM + h * DHEAD;
    const __half* Vb = vt + (size_t)bh * DHEAD * NSEQ;

    // Stage Q: 128 rows x 64 halves, swizzled
    #pragma unroll
    for (int i = 0; i < 4; i++) {
        const int id = tid + i * 256;     // 0..1023
        const int r  = id >> 3;           // 0..127
        const int ck = id & 7;
        const int off = r * 128 + ((ck ^ (r & 7)) * 16);
        cp_async16(QP + off, Qb + (size_t)r * HDIM + ck * 8);
    }
    CP_COMMIT();
    load_kv_h(Kb, Vb, 0, stage, tid);
    CP_COMMIT();

    // Wait for Q (KV0 still in flight), extract Q fragments
    CP_WAIT(1);
    __syncthreads();
    uint32_t aq[4][4];
    #pragma unroll
    for (int ks = 0; ks < 4; ks++) {
        const int ck   = ks * 2;
        const int swz0 = ((ck ^ (row & 7)) * 16) + 4 * col;
        const int swz1 = (((ck + 1) ^ (row & 7)) * 16) + 4 * col;
        const char* ap0 = QP + (warp * 16 + row) * 128;
        const char* ap8 = ap0 + 8 * 128;
        aq[ks][0] = *(const uint32_t*)(ap0 + swz0);
        aq[ks][1] = *(const uint32_t*)(ap8 + swz0);
        aq[ks][2] = *(const uint32_t*)(ap0 + swz1);
        aq[ks][3] = *(const uint32_t*)(ap8 + swz1);
    }
    __syncthreads();   // Q region now reusable as P buffer

    float m0r = -1e30f, m1r = -1e30f, l0 = 0.0f, l1 = 0.0f;
    float cacc[8][4];
    #pragma unroll
    for (int nt = 0; nt < 8; nt++)
        #pragma unroll
        for (int j = 0; j < 4; j++) cacc[nt][j] = 0.0f;

    const float* bias_b = attn_bias + (size_t)bh * NSEQ * NSEQ
                        + (size_t)(m0 + warp * 16 + row) * NSEQ;
    char* Pw = QP + warp * 2048;   // per-warp 16 rows x 128 B

    for (int c = 0; c < 4; c++) {
        CP_WAIT(0);
        __syncthreads();
        if (c < 3) {
            load_kv_h(Kb, Vb, (c + 1) * 64, stage + ((c + 1) & 1) * FA_STAGE, tid);
            CP_COMMIT();
        }

        const char* Ksb = stage + (c & 1) * FA_STAGE;
        const char* Vsb = Ksb + 8192;

        // S = Q · K^T over this 64-key chunk
        float s[8][4];
        #pragma unroll
        for (int nt = 0; nt < 8; nt++)
            #pragma unroll
            for (int j = 0; j < 4; j++) s[nt][j] = 0.0f;

        #pragma unroll
        for (int ks = 0; ks < 4; ks++) {
            const int ck   = ks * 2;
            const int swz0 = ((ck ^ (row & 7)) * 16) + 4 * col;
            const int swz1 = (((ck + 1) ^ (row & 7)) * 16) + 4 * col;
            uint32_t bfr[8][2];
            #pragma unroll
            for (int nt = 0; nt < 8; nt++) {
                const char* bp = Ksb + (nt * 8 + row) * 128;
                bfr[nt][0] = *(const uint32_t*)(bp + swz0);
                bfr[nt][1] = *(const uint32_t*)(bp + swz1);
            }
            #pragma unroll
            for (int nt = 0; nt < 8; nt++)
                mma_f16(s[nt], aq[ks], bfr[nt]);
        }

        // + bias, chunk row-max
        float mx0 = -1e30f, mx1 = -1e30f;
        #pragma unroll
        for (int nt = 0; nt < 8; nt++) {
            const float* bp = bias_b + c * 64 + nt * 8 + 2 * col;
            const float2 b0 = *(const float2*)bp;
            const float2 b1 = *(const float2*)(bp + 8 * NSEQ);
            s[nt][0] += b0.x; s[nt][1] += b0.y;
            s[nt][2] += b1.x; s[nt][3] += b1.y;
            mx0 = fmaxf(mx0, fmaxf(s[nt][0], s[nt][1]));
            mx1 = fmaxf(mx1, fmaxf(s[nt][2], s[nt][3]));
        }
        mx0 = fmaxf(mx0, __shfl_xor_sync(0xffffffffu, mx0, 1));
        mx0 = fmaxf(mx0, __shfl_xor_sync(0xffffffffu, mx0, 2));
        mx1 = fmaxf(mx1, __shfl_xor_sync(0xffffffffu, mx1, 1));
        mx1 = fmaxf(mx1, __shfl_xor_sync(0xffffffffu, mx1, 2));

        const float mn0 = fmaxf(m0r, mx0);
        const float mn1 = fmaxf(m1r, mx1);
        const float f0 = __expf(m0r - mn0);
        const float f1 = __expf(m1r - mn1);
        m0r = mn0; m1r = mn1;

        float sum0 = 0.0f, sum1 = 0.0f;
        #pragma unroll
        for (int nt = 0; nt < 8; nt++) {
            s[nt][0] = __expf(s[nt][0] - mn0);
            s[nt][1] = __expf(s[nt][1] - mn0);
            s[nt][2] = __expf(s[nt][2] - mn1);
            s[nt][3] = __expf(s[nt][3] - mn1);
            sum0 += s[nt][0] + s[nt][1];
            sum1 += s[nt][2] + s[nt][3];
        }
        l0 = l0 * f0 + sum0;
        l1 = l1 * f1 + sum1;
        #pragma unroll
        for (int nt = 0; nt < 8; nt++) {
            cacc[nt][0] *= f0; cacc[nt][1] *= f0;
            cacc[nt][2] *= f1; cacc[nt][3] *= f1;
        }

        // Store P tile (warp-private, 16 rows x 64 halves, swizzled)
        #pragma unroll
        for (int nt = 0; nt < 8; nt++) {
            const int swzp = ((nt ^ (row & 7)) * 16) + 4 * col;
            *(__half2*)(Pw + row * 128 + swzp) =
                __floats2half2_rn(s[nt][0], s[nt][1]);
            *(__half2*)(Pw + (row + 8) * 128 + swzp) =
                __floats2half2_rn(s[nt][2], s[nt][3]);
        }
        __syncwarp();

        // ctx += P · V
        #pragma unroll
        for (int ks = 0; ks < 4; ks++) {
            const int ck   = ks * 2;
            const int swz0 = ((ck ^ (row & 7)) * 16) + 4 * col;
            const int swz1 = (((ck + 1) ^ (row & 7)) * 16) + 4 * col;
            const char* pp0 = Pw + row * 128;
            const char* pp8 = pp0 + 8 * 128;
            uint32_t a[4];
            a[0] = *(const uint32_t*)(pp0 + swz0);
            a[1] = *(const uint32_t*)(pp8 + swz0);
            a[2] = *(const uint32_t*)(pp0 + swz1);
            a[3] = *(const uint32_t*)(pp8 + swz1);
            uint32_t bfr[8][2];
            #pragma unroll
            for (int nt = 0; nt < 8; nt++) {
                const char* bp = Vsb + (nt * 8 + row) * 128;
                bfr[nt][0] = *(const uint32_t*)(bp + swz0);
                bfr[nt][1] = *(const uint32_t*)(bp + swz1);
            }
            #pragma unroll
            for (int nt = 0; nt < 8; nt++)
                mma_f16(cacc[nt], a, bfr[nt]);
        }
        __syncwarp();
    }

    // Final normalize + write ctx [b][q][h*64+d] (fp16)
    l0 += __shfl_xor_sync(0xffffffffu, l0, 1);
    l0 += __shfl_xor_sync(0xffffffffu, l0, 2);
    l1 += __shfl_xor_sync(0xffffffffu, l1, 1);
    l1 += __shfl_xor_sync(0xffffffffu, l1, 2);
    const float inv0 = 1.0f / l0;
    const float inv1 = 1.0f / l1;

    __half* Cb = ctx + (size_t)b * NSEQ * HDIM + h * DHEAD
               + (size_t)(m0 + warp * 16 + row) * HDIM;
    #pragma unroll
    for (int nt = 0; nt < 8; nt++) {
        const int nb = nt * 8 + 2 * col;
        *(__half2*)(Cb + nb) =
            __floats2half2_rn(cacc[nt][0] * inv0, cacc[nt][1] * inv0);
        *(__half2*)(Cb + 8 * HDIM + nb) =
            __floats2half2_rn(cacc[nt][2] * inv1, cacc[nt][3] * inv1);
    }
}

// ---------------------------------------------------------------------------
// Weight transpose + fp16 convert: dst[n][k] = half(src[k][n]) per layer
// ---------------------------------------------------------------------------
__global__ void transpose_kernel(const float* __restrict__ src,
                                 __half* __restrict__ dst, int R, int C) {
    __shared__ float t[32][33];
    const size_t lo = (size_t)blockIdx.z * R * C;
    const int c0 = blockIdx.x * 32, r0 = blockIdx.y * 32;
    #pragma unroll
    for (int i = 0; i < 32; i += 8)
        t[threadIdx.y + i][threadIdx.x] =
            src[lo + (size_t)(r0 + threadIdx.y + i) * C + c0 + threadIdx.x];
    __syncthreads();
    #pragma unroll
    for (int i = 0; i < 32; i += 8)
        dst[lo + (size_t)(c0 + threadIdx.y + i) * R + r0 + threadIdx.x] =
            __float2half_rn(t[threadIdx.x][threadIdx.y + i]);
}

// ---------------------------------------------------------------------------
// LayerNorm: one block (256 threads) per row of 512; exact two-pass, fp16 out
// ---------------------------------------------------------------------------
__global__ void ln_kernel(const float* __restrict__ x,
                          const float* __restrict__ gs,
                          const float* __restrict__ gb,
                          __half* __restrict__ y) {
    __shared__ float red[8];
    const int row = blockIdx.x;
    const int tid = threadIdx.x;
    const float* xr = x + (size_t)row * HDIM;

    float v0 = xr[tid];
    float v1 = xr[tid + 256];

    float s = v0 + v1;
    #pragma unroll
    for (int o = 16; o; o >>= 1) s += __shfl_xor_sync(0xffffffffu, s, o);
    if ((tid & 31) == 0) red[tid >> 5] = s;
    __syncthreads();
    if (tid < 8) {
        float t = red[tid];
        #pragma unroll
        for (int o = 4; o; o >>= 1) t += __shfl_xor_sync(0xffu, t, o);
        if (tid == 0) red[0] = t;
    }
    __syncthreads();
    const float mu = red[0] * (1.0f / HDIM);
    __syncthreads();

    const float d0 = v0 - mu, d1 = v1 - mu;
    float sq = d0 * d0 + d1 * d1;
    #pragma unroll
    for (int o = 16; o; o >>= 1) sq += __shfl_xor_sync(0xffffffffu, sq, o);
    if ((tid & 31) == 0) red[tid >> 5] = sq;
    __syncthreads();
    if (tid < 8) {
        float t = red[tid];
        #pragma unroll
        for (int o = 4; o; o >>= 1) t += __shfl_xor_sync(0xffu, t, o);
        if (tid == 0) red[0] = t;
    }
    __syncthreads();
    const float inv = rsqrtf(red[0] * (1.0f / HDIM) + 1e-5f);

    __half* yr = y + (size_t)row * HDIM;
    yr[tid]       = __float2half_rn(d0 * inv * gs[tid]       + gb[tid]);
    yr[tid + 256] = __float2half_rn(d1 * inv * gs[tid + 256] + gb[tid + 256]);
}

// ---------------------------------------------------------------------------
// Host launcher
// ---------------------------------------------------------------------------
extern "C" void kernel_launch(void* const* d_in, const int* in_sizes, int n_in,
                              void* d_out, int out_size) {
    const float* x_in      = (const float*)d_in[0];
    const float* attn_bias = (const float*)d_in[1];
    const float* ln1_s     = (const float*)d_in[2];
    const float* ln1_b     = (const float*)d_in[3];
    const float* wq        = (const float*)d_in[4];
    const float* bq        = (const float*)d_in[5];
    const float* wk        = (const float*)d_in[6];
    const float* bk        = (const float*)d_in[7];
    const float* wv        = (const float*)d_in[8];
    const float* bv        = (const float*)d_in[9];
    const float* wo        = (const float*)d_in[10];
    const float* bo        = (const float*)d_in[11];
    const float* ln2_s     = (const float*)d_in[12];
    const float* ln2_b     = (const float*)d_in[13];
    const float* w1        = (const float*)d_in[14];
    const float* b1        = (const float*)d_in[15];
    const float* w2        = (const float*)d_in[16];
    const float* b2        = (const float*)d_in[17];

    float* X = (float*)d_out;

    __half *yb, *qb, *kb, *vb, *cb, *fb, *vt;
    __half *wqt, *wkt, *wvt, *wot, *w1t, *w2t;
    cudaGetSymbolAddress((void**)&yb, g_y);
    cudaGetSymbolAddress((void**)&qb, g_q);
    cudaGetSymbolAddress((void**)&kb, g_k);
    cudaGetSymbolAddress((void**)&vb, g_v);
    cudaGetSymbolAddress((void**)&cb, g_ctx);
    cudaGetSymbolAddress((void**)&fb, g_ffn);
    cudaGetSymbolAddress((void**)&vt, g_vt);
    cudaGetSymbolAddress((void**)&wqt, g_wqt);
    cudaGetSymbolAddress((void**)&wkt, g_wkt);
    cudaGetSymbolAddress((void**)&wvt, g_wvt);
    cudaGetSymbolAddress((void**)&wot, g_wot);
    cudaGetSymbolAddress((void**)&w1t, g_w1t);
    cudaGetSymbolAddress((void**)&w2t, g_w2t);

    cudaFuncSetAttribute(tgemm_kernel<2>,
                         cudaFuncAttributeMaxDynamicSharedMemorySize, GSMEM3);
    cudaFuncSetAttribute(tgemm_kernel<3>,
                         cudaFuncAttributeMaxDynamicSharedMemorySize, GSMEM3);
    cudaFuncSetAttribute(qkv_kernel,
                         cudaFuncAttributeMaxDynamicSharedMemorySize, GSMEM3);
    cudaFuncSetAttribute(fattn_kernel,
                         cudaFuncAttributeMaxDynamicSharedMemorySize, FA_SMEM);

    cudaMemcpyAsync(X, x_in, (size_t)MROWS * HDIM * sizeof(float),
                    cudaMemcpyDeviceToDevice);

    // One-time weight transposes (+ fp16 convert)
    {
        const dim3 tb(32, 8);
        const dim3 gHH(HDIM / 32, HDIM / 32, LNUM);
        const dim3 gHF(FDIM / 32, HDIM / 32, LNUM);
        const dim3 gFH(HDIM / 32, FDIM / 32, LNUM);
        transpose_kernel<<<gHH, tb>>>(wq, wqt, HDIM, HDIM);
        transpose_kernel<<<gHH, tb>>>(wk, wkt, HDIM, HDIM);
        transpose_kernel<<<gHH, tb>>>(wv, wvt, HDIM, HDIM);
        transpose_kernel<<<gHH, tb>>>(wo, wot, HDIM, HDIM);
        transpose_kernel<<<gHF, tb>>>(w1, w1t, HDIM, FDIM);
        transpose_kernel<<<gFH, tb>>>(w2, w2t, FDIM, HDIM);
    }

    const dim3 gB(256);
    const dim3 tG(128);
    const dim3 gQKV(12, MROWS / 128);            // (12, 64)
    const dim3 gProj(HDIM / 128, MROWS / 128);   // (4, 64)
    const dim3 gFfn1(FDIM / 128, MROWS / 128);   // (16, 64)
    const dim3 gFA(NSEQ / 128, NBH);             // (2, 256)
    const dim3 gVt(NSEQ / 32, DHEAD / 32, NBH);
    const dim3 tVt(32, 8);

    for (int l = 0; l < LNUM; l++) {
        const __half* wqt_l = wqt + (size_t)l * HDIM * HDIM;
        const __half* wkt_l = wkt + (size_t)l * HDIM * HDIM;
        const __half* wvt_l = wvt + (size_t)l * HDIM * HDIM;
        const __half* wot_l = wot + (size_t)l * HDIM * HDIM;
        const __half* w1t_l = w1t + (size_t)l * HDIM * FDIM;
        const __half* w2t_l = w2t + (size_t)l * FDIM * HDIM;

        // --- attention block ---
        ln_kernel<<<MROWS, gB>>>(X, ln1_s + l * HDIM, ln1_b + l * HDIM, yb);
        qkv_kernel<<<gQKV, tG, GSMEM3>>>(yb, wqt_l, wkt_l, wvt_l,
                                         bq + l * HDIM, bk + l * HDIM, bv + l * HDIM,
                                         qb, kb, vb);
        vt_kernel<<<gVt, tVt>>>(vb, vt);
        fattn_kernel<<<gFA, gB, FA_SMEM>>>(qb, kb, vt, attn_bias, cb);
        tgemm_kernel<3><<<gProj, tG, GSMEM3>>>(cb, wot_l, bo + l * HDIM, X,
                                               HDIM, HDIM);

        // --- FFN block ---
        ln_kernel<<<MROWS, gB>>>(X, ln2_s + l * HDIM, ln2_b + l * HDIM, yb);
        tgemm_kernel<2><<<gFfn1, tG, GSMEM3>>>(yb, w1t_l, b1 + l * FDIM, fb,
                                               FDIM, HDIM);
        tgemm_kernel<3><<<gProj, tG, GSMEM3>>>(fb, w2t_l, b2 + l * HDIM, X,
                                               HDIM, FDIM);
    }
}